// round 7
// baseline (speedup 1.0000x reference)
#include <cuda_runtime.h>
#include <cuda_bf16.h>

// ---------------------------------------------------------------------------
// MLP-Mixer on tensor cores (mma.sync m16n8k16 bf16, fp32 accum), 3-pass
// bf16 hi/lo split: C = Ah@Bh + Ah@Bl + Al@Bh.
// Round 6: 384 threads (12 warps, 12 elems/CTA, 3 warps/SMSP) and interleaved
// hi/lo weight layout so each (kt,nt) fragment group is 2x LDS.64 feeding
// 6 MMAs (was 6x LDS.32). Row strides 160B / 1056B: conflict-free LDS.64.
// Pre (conv+fc0) and head (fc1+pool+fcout) stay on the fp32 FFMA2 path.
// ---------------------------------------------------------------------------

#define MIX_EPS 1e-5f
#define NTHREADS 384
#define NWARPS 12

// ---- SMEM byte offsets ----
#define OFF_H     0         // 12 * 32*34 * 4 = 52224
#define OFF_ST    52224     // 12 * 64 * 4 = 3072
#define OFF_B1T   55296     // 256 f
#define OFF_B1C   56320
#define OFF_B2T   57344     // 32 f
#define OFF_B2C   57472
#define OFF_LN1G  57600
#define OFF_LN1B  57728
#define OFF_LN2G  57856
#define OFF_LN2B  57984
#define OFF_WT    58112     // weight region (also fp32 staging for pre/head)
#define OFF_W1T   58112     // 256 rows * 80 halves * 2B = 40960
#define OFF_W1C   99072     // 40960
#define OFF_W2T   140032    // 32 rows * 528 halves * 2B = 33792
#define OFF_W2C   173824    // 33792
#define SMEM_BYTES 207616

__device__ __forceinline__ float2 ffma2(float2 a, float2 b, float2 c) {
    unsigned long long au = *reinterpret_cast<unsigned long long*>(&a);
    unsigned long long bu = *reinterpret_cast<unsigned long long*>(&b);
    unsigned long long cu = *reinterpret_cast<unsigned long long*>(&c);
    unsigned long long du;
    asm("fma.rn.f32x2 %0, %1, %2, %3;" : "=l"(du) : "l"(au), "l"(bu), "l"(cu));
    return *reinterpret_cast<float2*>(&du);
}
__device__ __forceinline__ float2 fadd2(float2 a, float2 b) {
    unsigned long long au = *reinterpret_cast<unsigned long long*>(&a);
    unsigned long long bu = *reinterpret_cast<unsigned long long*>(&b);
    unsigned long long du;
    asm("add.rn.f32x2 %0, %1, %2;" : "=l"(du) : "l"(au), "l"(bu));
    return *reinterpret_cast<float2*>(&du);
}

__device__ __forceinline__ void mma16816(float d[4], const unsigned a[4],
                                         unsigned b0, unsigned b1) {
    asm volatile(
        "mma.sync.aligned.m16n8k16.row.col.f32.bf16.bf16.f32 "
        "{%0,%1,%2,%3}, {%4,%5,%6,%7}, {%8,%9}, {%0,%1,%2,%3};\n"
        : "+f"(d[0]), "+f"(d[1]), "+f"(d[2]), "+f"(d[3])
        : "r"(a[0]), "r"(a[1]), "r"(a[2]), "r"(a[3]), "r"(b0), "r"(b1));
}

// One mixing branch (tensor cores). Interleaved weight layout:
//   w1: row n (256 rows) = 80 halves; k-pair p (0..15) at offset p*4:
//       [hi(2p), hi(2p+1), lo(2p), lo(2p+1)]
//   w2: row n (32 rows) = 528 halves; k-pair p (0..127) at offset p*4.
// w2 is pre-scaled by 1/6.
template <bool TOKEN>
__device__ __forceinline__ void mix_branch_mma(
    float* h, float* st,
    const __nv_bfloat16* w1, const __nv_bfloat16* w2,
    const float* b1, const float* b2,
    const float* g, const float* bb, int lane)
{
    const int gid = lane >> 2;
    const int tg  = lane & 3;

    // ---- LN stats (lane = row) ----
    float s = 0.f, q = 0.f;
    #pragma unroll
    for (int j = 0; j < 32; j += 2) {
        float2 v = *reinterpret_cast<const float2*>(h + lane * 34 + j);
        s += v.x + v.y; q += v.x * v.x + v.y * v.y;
    }
    float m = s * 0.03125f;
    float r = rsqrtf(fmaxf(q * 0.03125f - m * m, 0.f) + MIX_EPS);
    st[lane] = m; st[32 + lane] = r;
    __syncwarp();

    // ---- A1 fragments (LN output, hi/lo split) ----
    unsigned a1h[2][2][4], a1l[2][2][4];
    #pragma unroll
    for (int mt = 0; mt < 2; mt++)
    #pragma unroll
    for (int kt = 0; kt < 2; kt++) {
        #pragma unroll
        for (int rr = 0; rr < 2; rr++) {
            int am = mt * 16 + gid + rr * 8;
            #pragma unroll
            for (int cc = 0; cc < 2; cc++) {
                int ak = kt * 16 + tg * 2 + cc * 8;
                float v0, v1;
                if (TOKEN) {
                    float x0 = h[ak * 34 + am];
                    float x1 = h[(ak + 1) * 34 + am];
                    float gm = g[am], bm = bb[am];
                    v0 = (x0 - st[ak]) * st[32 + ak] * gm + bm;
                    v1 = (x1 - st[ak + 1]) * st[32 + ak + 1] * gm + bm;
                } else {
                    float2 x = *reinterpret_cast<const float2*>(h + am * 34 + ak);
                    float mm = st[am], ri = st[32 + am];
                    v0 = (x.x - mm) * ri * g[ak] + bb[ak];
                    v1 = (x.y - mm) * ri * g[ak + 1] + bb[ak + 1];
                }
                __nv_bfloat162 hi2 = __floats2bfloat162_rn(v0, v1);
                float l0 = v0 - __bfloat162float(hi2.x);
                float l1 = v1 - __bfloat162float(hi2.y);
                __nv_bfloat162 lo2 = __floats2bfloat162_rn(l0, l1);
                int ri2 = rr + cc * 2;
                a1h[mt][kt][ri2] = *reinterpret_cast<unsigned*>(&hi2);
                a1l[mt][kt][ri2] = *reinterpret_cast<unsigned*>(&lo2);
            }
        }
    }

    // ---- out accumulators, init with bias b2 ----
    float outacc[2][4][4];
    #pragma unroll
    for (int ntO = 0; ntO < 4; ntO++) {
        int c = ntO * 8 + tg * 2;
        float bv0 = b2[c], bv1 = b2[c + 1];
        #pragma unroll
        for (int mt = 0; mt < 2; mt++) {
            outacc[mt][ntO][0] = bv0; outacc[mt][ntO][1] = bv1;
            outacc[mt][ntO][2] = bv0; outacc[mt][ntO][3] = bv1;
        }
    }

    // ---- hidden loop over DIM=256 in 4 chunks of 64 ----
    for (int nc = 0; nc < 4; nc++) {
        float dAcc[2][8][4];
        #pragma unroll
        for (int mt = 0; mt < 2; mt++)
        #pragma unroll
        for (int nt = 0; nt < 8; nt++)
        #pragma unroll
        for (int k = 0; k < 4; k++) dAcc[mt][nt][k] = 0.f;

        // gemm1: per (kt,nt) load hi+lo fragments once, issue all 3 passes
        #pragma unroll
        for (int kt = 0; kt < 2; kt++) {
            #pragma unroll
            for (int nt = 0; nt < 8; nt++) {
                int n = nc * 64 + nt * 8 + gid;
                const uint2* qp = reinterpret_cast<const uint2*>(
                    w1 + n * 80 + (tg + 8 * kt) * 4);
                uint2 f0 = qp[0];   // [hi01 | lo01] at k0
                uint2 f1 = qp[4];   // [hi01 | lo01] at k0+8
                mma16816(dAcc[0][nt], a1h[0][kt], f0.x, f1.x);
                mma16816(dAcc[1][nt], a1h[1][kt], f0.x, f1.x);
                mma16816(dAcc[0][nt], a1h[0][kt], f0.y, f1.y);
                mma16816(dAcc[1][nt], a1h[1][kt], f0.y, f1.y);
                mma16816(dAcc[0][nt], a1l[0][kt], f0.x, f1.x);
                mma16816(dAcc[1][nt], a1l[1][kt], f0.x, f1.x);
            }
        }

        // epilogue + gemm2, one kt2 (16 hidden cols) at a time
        #pragma unroll
        for (int kt2 = 0; kt2 < 4; kt2++) {
            unsigned a2h[2][4], a2l[2][4];
            #pragma unroll
            for (int part = 0; part < 2; part++) {
                int nt = 2 * kt2 + part;
                int c = nc * 64 + nt * 8 + tg * 2;
                float2 bv = *reinterpret_cast<const float2*>(b1 + c);
                #pragma unroll
                for (int mt = 0; mt < 2; mt++) {
                    float v0 = dAcc[mt][nt][0] + bv.x;
                    float v1 = dAcc[mt][nt][1] + bv.y;
                    float v2 = dAcc[mt][nt][2] + bv.x;
                    float v3 = dAcc[mt][nt][3] + bv.y;
                    float h0 = v0 * fminf(fmaxf(v0 + 3.f, 0.f), 6.f);
                    float h1 = v1 * fminf(fmaxf(v1 + 3.f, 0.f), 6.f);
                    float h2 = v2 * fminf(fmaxf(v2 + 3.f, 0.f), 6.f);
                    float h3 = v3 * fminf(fmaxf(v3 + 3.f, 0.f), 6.f);
                    __nv_bfloat162 p01 = __floats2bfloat162_rn(h0, h1);
                    __nv_bfloat162 p23 = __floats2bfloat162_rn(h2, h3);
                    float r0 = h0 - __bfloat162float(p01.x);
                    float r1 = h1 - __bfloat162float(p01.y);
                    float r2 = h2 - __bfloat162float(p23.x);
                    float r3 = h3 - __bfloat162float(p23.y);
                    __nv_bfloat162 q01 = __floats2bfloat162_rn(r0, r1);
                    __nv_bfloat162 q23 = __floats2bfloat162_rn(r2, r3);
                    a2h[mt][part * 2 + 0] = *reinterpret_cast<unsigned*>(&p01);
                    a2h[mt][part * 2 + 1] = *reinterpret_cast<unsigned*>(&p23);
                    a2l[mt][part * 2 + 0] = *reinterpret_cast<unsigned*>(&q01);
                    a2l[mt][part * 2 + 1] = *reinterpret_cast<unsigned*>(&q23);
                }
            }
            #pragma unroll
            for (int ntO = 0; ntO < 4; ntO++) {
                int n = ntO * 8 + gid;
                int p = nc * 32 + kt2 * 8 + tg;
                const uint2* qp = reinterpret_cast<const uint2*>(
                    w2 + n * 528 + p * 4);
                uint2 f0 = qp[0];
                uint2 f1 = qp[4];
                mma16816(outacc[0][ntO], a2h[0], f0.x, f1.x);
                mma16816(outacc[1][ntO], a2h[1], f0.x, f1.x);
                mma16816(outacc[0][ntO], a2h[0], f0.y, f1.y);
                mma16816(outacc[1][ntO], a2h[1], f0.y, f1.y);
                mma16816(outacc[0][ntO], a2l[0], f0.x, f1.x);
                mma16816(outacc[1][ntO], a2l[1], f0.x, f1.x);
            }
        }
    }

    // ---- residual add back into h ----
    if (TOKEN) {
        #pragma unroll
        for (int mt = 0; mt < 2; mt++)
        #pragma unroll
        for (int ntO = 0; ntO < 4; ntO++) {
            int mm = mt * 16 + gid;
            int nn = ntO * 8 + tg * 2;
            h[nn * 34 + mm]           += outacc[mt][ntO][0];
            h[(nn + 1) * 34 + mm]     += outacc[mt][ntO][1];
            h[nn * 34 + mm + 8]       += outacc[mt][ntO][2];
            h[(nn + 1) * 34 + mm + 8] += outacc[mt][ntO][3];
        }
    } else {
        #pragma unroll
        for (int mt = 0; mt < 2; mt++)
        #pragma unroll
        for (int ntO = 0; ntO < 4; ntO++) {
            int rr0 = mt * 16 + gid;
            int c = ntO * 8 + tg * 2;
            float2* p0 = reinterpret_cast<float2*>(h + rr0 * 34 + c);
            float2 v0 = *p0;
            v0.x += outacc[mt][ntO][0]; v0.y += outacc[mt][ntO][1];
            *p0 = v0;
            float2* p1 = reinterpret_cast<float2*>(h + (rr0 + 8) * 34 + c);
            float2 v1 = *p1;
            v1.x += outacc[mt][ntO][2]; v1.y += outacc[mt][ntO][3];
            *p1 = v1;
        }
    }
    __syncwarp();
}

extern __shared__ char smem_raw[];

__global__ __launch_bounds__(NTHREADS, 1)
void mixer_kernel(
    const float* __restrict__ x,
    const float* __restrict__ conv_w, const float* __restrict__ conv_b,
    const float* __restrict__ fc0_w,  const float* __restrict__ fc0_b,
    const float* __restrict__ ln1_g,  const float* __restrict__ ln1_b,
    const float* __restrict__ w11,    const float* __restrict__ b11,
    const float* __restrict__ w12,    const float* __restrict__ b12,
    const float* __restrict__ ln2_g,  const float* __restrict__ ln2_b,
    const float* __restrict__ w21,    const float* __restrict__ b21,
    const float* __restrict__ w22,    const float* __restrict__ b22,
    const float* __restrict__ fc1_w,  const float* __restrict__ fc1_b,
    const float* __restrict__ fcout_w,const float* __restrict__ fcout_b,
    float* __restrict__ out, int B)
{
    const int tid = threadIdx.x;
    const int lane = tid & 31;
    const int wid = tid >> 5;      // 0..11, one element per warp

    float* sH   = reinterpret_cast<float*>(smem_raw + OFF_H);
    float* sSt  = reinterpret_cast<float*>(smem_raw + OFF_ST);
    float* sB1t = reinterpret_cast<float*>(smem_raw + OFF_B1T);
    float* sB1c = reinterpret_cast<float*>(smem_raw + OFF_B1C);
    float* sB2t = reinterpret_cast<float*>(smem_raw + OFF_B2T);
    float* sB2c = reinterpret_cast<float*>(smem_raw + OFF_B2C);
    float* sL1g = reinterpret_cast<float*>(smem_raw + OFF_LN1G);
    float* sL1b = reinterpret_cast<float*>(smem_raw + OFF_LN1B);
    float* sL2g = reinterpret_cast<float*>(smem_raw + OFF_LN2G);
    float* sL2b = reinterpret_cast<float*>(smem_raw + OFF_LN2B);
    __nv_bfloat16* w1t = reinterpret_cast<__nv_bfloat16*>(smem_raw + OFF_W1T);
    __nv_bfloat16* w1c = reinterpret_cast<__nv_bfloat16*>(smem_raw + OFF_W1C);
    __nv_bfloat16* w2t = reinterpret_cast<__nv_bfloat16*>(smem_raw + OFF_W2T);
    __nv_bfloat16* w2c = reinterpret_cast<__nv_bfloat16*>(smem_raw + OFF_W2C);
    float* sFw = reinterpret_cast<float*>(smem_raw + OFF_WT);
    float* sFo = reinterpret_cast<float*>(smem_raw + OFF_WT + 16384);

    const int eb = blockIdx.x * NWARPS + wid;
    const bool act = (eb < B);
    float* h  = sH + wid * (32 * 34);
    float* st = sSt + wid * 64;

    // ---- stage fc0 weights, preprocess (conv1x1 + fc0) ----
    for (int i = tid; i < 1024; i += NTHREADS) sFw[i] = fc0_w[i];
    if (tid < 32) sB1t[tid] = fc0_b[tid];
    __syncthreads();

    if (act) {
        const float cw0 = conv_w[0], cw1 = conv_w[1], cw2 = conv_w[2];
        const float cb  = conv_b[0];
        const float* xb = x + (size_t)eb * 3072 + lane * 32;
        float2 gp[16];
        #pragma unroll
        for (int qq = 0; qq < 8; qq++) {
            float4 v0 = *reinterpret_cast<const float4*>(xb + qq * 4);
            float4 v1 = *reinterpret_cast<const float4*>(xb + 1024 + qq * 4);
            float4 v2 = *reinterpret_cast<const float4*>(xb + 2048 + qq * 4);
            gp[2 * qq]     = make_float2(cw0 * v0.x + cw1 * v1.x + cw2 * v2.x + cb,
                                         cw0 * v0.y + cw1 * v1.y + cw2 * v2.y + cb);
            gp[2 * qq + 1] = make_float2(cw0 * v0.z + cw1 * v1.z + cw2 * v2.z + cb,
                                         cw0 * v0.w + cw1 * v1.w + cw2 * v2.w + cb);
        }
        for (int j = 0; j < 32; j++) {
            const float4* wq = reinterpret_cast<const float4*>(sFw + j * 32);
            float2 acc = make_float2(0.f, 0.f), accb = make_float2(0.f, 0.f);
            #pragma unroll
            for (int qq = 0; qq < 8; qq++) {
                float4 w = wq[qq];
                acc  = ffma2(gp[2 * qq],     make_float2(w.x, w.y), acc);
                accb = ffma2(gp[2 * qq + 1], make_float2(w.z, w.w), accb);
            }
            float2 sv = fadd2(acc, accb);
            h[lane * 34 + j] = sv.x + sv.y + sB1t[j];
        }
    }
    __syncthreads();

    // ---- 8 layers x 2 repeats ----
    for (int l = 0; l < 8; l++) {
        // stage bf16 hi/lo interleaved weight planes for this layer
        {
            const float* g11 = w11 + l * 8192;
            const float* g21 = w21 + l * 8192;
            for (int i = tid; i < 8192; i += NTHREADS) {
                int d = i >> 5, k = i & 31;
                int idx = d * 80 + (k >> 1) * 4 + (k & 1);
                float v = g11[i];
                __nv_bfloat16 hi = __float2bfloat16(v);
                w1t[idx]     = hi;
                w1t[idx + 2] = __float2bfloat16(v - __bfloat162float(hi));
                float u = g21[i];
                __nv_bfloat16 hu = __float2bfloat16(u);
                w1c[idx]     = hu;
                w1c[idx + 2] = __float2bfloat16(u - __bfloat162float(hu));
            }
            const float* g12 = w12 + l * 8192;
            const float* g22 = w22 + l * 8192;
            for (int i = tid; i < 8192; i += NTHREADS) {
                int n = i >> 8, k = i & 255;
                int idx = n * 528 + (k >> 1) * 4 + (k & 1);
                float v = g12[i] * (1.0f / 6.0f);
                __nv_bfloat16 hi = __float2bfloat16(v);
                w2t[idx]     = hi;
                w2t[idx + 2] = __float2bfloat16(v - __bfloat162float(hi));
                float u = g22[i] * (1.0f / 6.0f);
                __nv_bfloat16 hu = __float2bfloat16(u);
                w2c[idx]     = hu;
                w2c[idx + 2] = __float2bfloat16(u - __bfloat162float(hu));
            }
            if (tid < 256) { sB1t[tid] = b11[l * 256 + tid]; sB1c[tid] = b21[l * 256 + tid]; }
            if (tid < 32) {
                sB2t[tid] = b12[l * 32 + tid];
                sB2c[tid] = b22[l * 32 + tid];
                sL1g[tid] = ln1_g[l * 32 + tid];
                sL1b[tid] = ln1_b[l * 32 + tid];
                sL2g[tid] = ln2_g[l * 32 + tid];
                sL2b[tid] = ln2_b[l * 32 + tid];
            }
        }
        __syncthreads();

        if (act) {
            for (int rep = 0; rep < 2; rep++) {
                mix_branch_mma<true >(h, st, w1t, w2t, sB1t, sB2t, sL1g, sL1b, lane);
                mix_branch_mma<false>(h, st, w1c, w2c, sB1c, sB2c, sL2g, sL2b, lane);
            }
        }
        __syncthreads();
    }

    // ---- head: fc1 + hardswish + avgpool(32) + fcout ----
    {
        const float4* s1 = reinterpret_cast<const float4*>(fc1_w);
        float4* d1 = reinterpret_cast<float4*>(sFw);
        for (int i = tid; i < 1024; i += NTHREADS) d1[i] = s1[i];
        for (int i = tid; i < 1280; i += NTHREADS) sFo[i] = fcout_w[i];
        if (tid < 128) sB1t[tid] = fc1_b[tid];
        if (tid < 10)  sB2t[tid] = fcout_b[tid];
    }
    __syncthreads();

    if (act) {
        float2 ap[16];
        #pragma unroll
        for (int t = 0; t < 16; t++)
            ap[t] = *reinterpret_cast<const float2*>(h + lane * 34 + 2 * t);
        float pool[4] = {0.f, 0.f, 0.f, 0.f};
        for (int d = 0; d < 128; d++) {
            const float4* wq = reinterpret_cast<const float4*>(sFw + d * 32);
            float2 acc = make_float2(0.f, 0.f), accb = make_float2(0.f, 0.f);
            #pragma unroll
            for (int qq = 0; qq < 8; qq++) {
                float4 w = wq[qq];
                acc  = ffma2(ap[2 * qq],     make_float2(w.x, w.y), acc);
                accb = ffma2(ap[2 * qq + 1], make_float2(w.z, w.w), accb);
            }
            float2 sv = fadd2(acc, accb);
            float v = sv.x + sv.y + sB1t[d];
            float y = v * fminf(fmaxf(v + 3.0f, 0.0f), 6.0f) * (1.0f / 6.0f);
            pool[d >> 5] += y;
        }
        #pragma unroll
        for (int p = 0; p < 4; p++) pool[p] *= (1.0f / 32.0f);
        #pragma unroll
        for (int o = 0; o < 10; o++) {
            float4 wv = *reinterpret_cast<const float4*>(sFo + o * 128 + lane * 4);
            float v = pool[0] * wv.x + pool[1] * wv.y + pool[2] * wv.z + pool[3] * wv.w;
            #pragma unroll
            for (int sft = 16; sft > 0; sft >>= 1)
                v += __shfl_xor_sync(0xffffffffu, v, sft);
            if (lane == 0) out[(size_t)eb * 10 + o] = v + sB2t[o];
        }
    }
}

extern "C" void kernel_launch(void* const* d_in, const int* in_sizes, int n_in,
                              void* d_out, int out_size) {
    const float* x       = (const float*)d_in[0];
    const float* conv_w  = (const float*)d_in[1];
    const float* conv_b  = (const float*)d_in[2];
    const float* fc0_w   = (const float*)d_in[3];
    const float* fc0_b   = (const float*)d_in[4];
    const float* ln1_g   = (const float*)d_in[5];
    const float* ln1_b   = (const float*)d_in[6];
    const float* w11     = (const float*)d_in[7];
    const float* b11     = (const float*)d_in[8];
    const float* w12     = (const float*)d_in[9];
    const float* b12     = (const float*)d_in[10];
    const float* ln2_g   = (const float*)d_in[11];
    const float* ln2_b   = (const float*)d_in[12];
    const float* w21     = (const float*)d_in[13];
    const float* b21     = (const float*)d_in[14];
    const float* w22     = (const float*)d_in[15];
    const float* b22     = (const float*)d_in[16];
    const float* fc1_w   = (const float*)d_in[17];
    const float* fc1_b   = (const float*)d_in[18];
    const float* fcout_w = (const float*)d_in[19];
    const float* fcout_b = (const float*)d_in[20];
    float* out = (float*)d_out;

    const int B = in_sizes[0] / 3072;
    const int blocks = (B + NWARPS - 1) / NWARPS;

    cudaFuncSetAttribute(mixer_kernel,
                         cudaFuncAttributeMaxDynamicSharedMemorySize,
                         SMEM_BYTES);
    mixer_kernel<<<blocks, NTHREADS, SMEM_BYTES>>>(
        x, conv_w, conv_b, fc0_w, fc0_b, ln1_g, ln1_b,
        w11, b11, w12, b12, ln2_g, ln2_b, w21, b21, w22, b22,
        fc1_w, fc1_b, fcout_w, fcout_b, out, B);
}

// round 8
// speedup vs baseline: 1.3788x; 1.3788x over previous
#include <cuda_runtime.h>
#include <cuda_fp16.h>

// ---------------------------------------------------------------------------
// MLP-Mixer on tensor cores, round 7: fp16 2-pass split (was bf16 3-pass).
// C = Ah @ (Bh + Bl): weights hi/lo fp16 (residual ~2^-22), activations
// single-rounded fp16 (~2^-11). 512 MMAs/branch (was 768).
// 384 threads, 12 warps, one element per warp. Interleaved hi/lo weight
// layout: each fragment group is 2x LDS.64 feeding 4 MMAs.
// Pre (conv+fc0) and head (fc1+pool+fcout) stay on the fp32 FFMA2 path.
// ---------------------------------------------------------------------------

#define MIX_EPS 1e-5f
#define NTHREADS 384
#define NWARPS 12

// ---- SMEM byte offsets ----
#define OFF_H     0         // 12 * 32*34 * 4 = 52224
#define OFF_ST    52224     // 12 * 64 * 4 = 3072
#define OFF_B1T   55296     // 256 f
#define OFF_B1C   56320
#define OFF_B2T   57344     // 32 f
#define OFF_B2C   57472
#define OFF_LN1G  57600
#define OFF_LN1B  57728
#define OFF_LN2G  57856
#define OFF_LN2B  57984
#define OFF_WT    58112     // weight region (also fp32 staging for pre/head)
#define OFF_W1T   58112     // 256 rows * 80 halves * 2B = 40960
#define OFF_W1C   99072     // 40960
#define OFF_W2T   140032    // 32 rows * 528 halves * 2B = 33792
#define OFF_W2C   173824    // 33792
#define SMEM_BYTES 207616

__device__ __forceinline__ float2 ffma2(float2 a, float2 b, float2 c) {
    unsigned long long au = *reinterpret_cast<unsigned long long*>(&a);
    unsigned long long bu = *reinterpret_cast<unsigned long long*>(&b);
    unsigned long long cu = *reinterpret_cast<unsigned long long*>(&c);
    unsigned long long du;
    asm("fma.rn.f32x2 %0, %1, %2, %3;" : "=l"(du) : "l"(au), "l"(bu), "l"(cu));
    return *reinterpret_cast<float2*>(&du);
}
__device__ __forceinline__ float2 fadd2(float2 a, float2 b) {
    unsigned long long au = *reinterpret_cast<unsigned long long*>(&a);
    unsigned long long bu = *reinterpret_cast<unsigned long long*>(&b);
    unsigned long long du;
    asm("add.rn.f32x2 %0, %1, %2;" : "=l"(du) : "l"(au), "l"(bu));
    return *reinterpret_cast<float2*>(&du);
}

__device__ __forceinline__ void mma16816(float d[4], const unsigned a[4],
                                         unsigned b0, unsigned b1) {
    asm volatile(
        "mma.sync.aligned.m16n8k16.row.col.f32.f16.f16.f32 "
        "{%0,%1,%2,%3}, {%4,%5,%6,%7}, {%8,%9}, {%0,%1,%2,%3};\n"
        : "+f"(d[0]), "+f"(d[1]), "+f"(d[2]), "+f"(d[3])
        : "r"(a[0]), "r"(a[1]), "r"(a[2]), "r"(a[3]), "r"(b0), "r"(b1));
}

// One mixing branch (tensor cores, fp16 2-pass). Interleaved weight layout:
//   w1: row n (256 rows) = 80 halves; k-pair p (0..15) at offset p*4:
//       [hi(2p), hi(2p+1), lo(2p), lo(2p+1)]
//   w2: row n (32 rows) = 528 halves; k-pair p (0..127) at offset p*4.
// w2 is pre-scaled by 1/6.
template <bool TOKEN>
__device__ __forceinline__ void mix_branch_mma(
    float* h, float* st,
    const __half* w1, const __half* w2,
    const float* b1, const float* b2,
    const float* g, const float* bb, int lane)
{
    const int gid = lane >> 2;
    const int tg  = lane & 3;

    // ---- LN stats (lane = row) ----
    float s = 0.f, q = 0.f;
    #pragma unroll
    for (int j = 0; j < 32; j += 2) {
        float2 v = *reinterpret_cast<const float2*>(h + lane * 34 + j);
        s += v.x + v.y; q += v.x * v.x + v.y * v.y;
    }
    float m = s * 0.03125f;
    float r = rsqrtf(fmaxf(q * 0.03125f - m * m, 0.f) + MIX_EPS);
    st[lane] = m; st[32 + lane] = r;
    __syncwarp();

    // ---- A1 fragments (LN output, single fp16 rounding) ----
    unsigned a1[2][2][4];
    #pragma unroll
    for (int mt = 0; mt < 2; mt++)
    #pragma unroll
    for (int kt = 0; kt < 2; kt++) {
        #pragma unroll
        for (int rr = 0; rr < 2; rr++) {
            int am = mt * 16 + gid + rr * 8;
            #pragma unroll
            for (int cc = 0; cc < 2; cc++) {
                int ak = kt * 16 + tg * 2 + cc * 8;
                float v0, v1;
                if (TOKEN) {
                    float x0 = h[ak * 34 + am];
                    float x1 = h[(ak + 1) * 34 + am];
                    float gm = g[am], bm = bb[am];
                    v0 = (x0 - st[ak]) * st[32 + ak] * gm + bm;
                    v1 = (x1 - st[ak + 1]) * st[32 + ak + 1] * gm + bm;
                } else {
                    float2 x = *reinterpret_cast<const float2*>(h + am * 34 + ak);
                    float mm = st[am], ri = st[32 + am];
                    v0 = (x.x - mm) * ri * g[ak] + bb[ak];
                    v1 = (x.y - mm) * ri * g[ak + 1] + bb[ak + 1];
                }
                __half2 hv = __floats2half2_rn(v0, v1);
                a1[mt][kt][rr + cc * 2] = *reinterpret_cast<unsigned*>(&hv);
            }
        }
    }

    // ---- out accumulators, init with bias b2 ----
    float outacc[2][4][4];
    #pragma unroll
    for (int ntO = 0; ntO < 4; ntO++) {
        int c = ntO * 8 + tg * 2;
        float bv0 = b2[c], bv1 = b2[c + 1];
        #pragma unroll
        for (int mt = 0; mt < 2; mt++) {
            outacc[mt][ntO][0] = bv0; outacc[mt][ntO][1] = bv1;
            outacc[mt][ntO][2] = bv0; outacc[mt][ntO][3] = bv1;
        }
    }

    // ---- hidden loop over DIM=256 in 4 chunks of 64 ----
    for (int nc = 0; nc < 4; nc++) {
        float dAcc[2][8][4];
        #pragma unroll
        for (int mt = 0; mt < 2; mt++)
        #pragma unroll
        for (int nt = 0; nt < 8; nt++)
        #pragma unroll
        for (int k = 0; k < 4; k++) dAcc[mt][nt][k] = 0.f;

        // gemm1: per (kt,nt): 2x LDS.64 -> 4 MMAs (Ah@Bh + Ah@Bl)
        #pragma unroll
        for (int kt = 0; kt < 2; kt++) {
            #pragma unroll
            for (int nt = 0; nt < 8; nt++) {
                int n = nc * 64 + nt * 8 + gid;
                const uint2* qp = reinterpret_cast<const uint2*>(
                    w1 + n * 80 + (tg + 8 * kt) * 4);
                uint2 f0 = qp[0];   // [hi01 | lo01] at k0
                uint2 f1 = qp[4];   // [hi01 | lo01] at k0+8
                mma16816(dAcc[0][nt], a1[0][kt], f0.x, f1.x);
                mma16816(dAcc[1][nt], a1[1][kt], f0.x, f1.x);
                mma16816(dAcc[0][nt], a1[0][kt], f0.y, f1.y);
                mma16816(dAcc[1][nt], a1[1][kt], f0.y, f1.y);
            }
        }

        // epilogue + gemm2, one kt2 (16 hidden cols) at a time
        #pragma unroll
        for (int kt2 = 0; kt2 < 4; kt2++) {
            unsigned a2[2][4];
            #pragma unroll
            for (int part = 0; part < 2; part++) {
                int nt = 2 * kt2 + part;
                int c = nc * 64 + nt * 8 + tg * 2;
                float2 bv = *reinterpret_cast<const float2*>(b1 + c);
                #pragma unroll
                for (int mt = 0; mt < 2; mt++) {
                    float v0 = dAcc[mt][nt][0] + bv.x;
                    float v1 = dAcc[mt][nt][1] + bv.y;
                    float v2 = dAcc[mt][nt][2] + bv.x;
                    float v3 = dAcc[mt][nt][3] + bv.y;
                    float h0 = v0 * fminf(fmaxf(v0 + 3.f, 0.f), 6.f);
                    float h1 = v1 * fminf(fmaxf(v1 + 3.f, 0.f), 6.f);
                    float h2 = v2 * fminf(fmaxf(v2 + 3.f, 0.f), 6.f);
                    float h3 = v3 * fminf(fmaxf(v3 + 3.f, 0.f), 6.f);
                    __half2 p01 = __floats2half2_rn(h0, h1);
                    __half2 p23 = __floats2half2_rn(h2, h3);
                    a2[mt][part * 2 + 0] = *reinterpret_cast<unsigned*>(&p01);
                    a2[mt][part * 2 + 1] = *reinterpret_cast<unsigned*>(&p23);
                }
            }
            #pragma unroll
            for (int ntO = 0; ntO < 4; ntO++) {
                int n = ntO * 8 + gid;
                int p = nc * 32 + kt2 * 8 + tg;
                const uint2* qp = reinterpret_cast<const uint2*>(
                    w2 + n * 528 + p * 4);
                uint2 f0 = qp[0];
                uint2 f1 = qp[4];
                mma16816(outacc[0][ntO], a2[0], f0.x, f1.x);
                mma16816(outacc[1][ntO], a2[1], f0.x, f1.x);
                mma16816(outacc[0][ntO], a2[0], f0.y, f1.y);
                mma16816(outacc[1][ntO], a2[1], f0.y, f1.y);
            }
        }
    }

    // ---- residual add back into h ----
    if (TOKEN) {
        #pragma unroll
        for (int mt = 0; mt < 2; mt++)
        #pragma unroll
        for (int ntO = 0; ntO < 4; ntO++) {
            int mm = mt * 16 + gid;
            int nn = ntO * 8 + tg * 2;
            h[nn * 34 + mm]           += outacc[mt][ntO][0];
            h[(nn + 1) * 34 + mm]     += outacc[mt][ntO][1];
            h[nn * 34 + mm + 8]       += outacc[mt][ntO][2];
            h[(nn + 1) * 34 + mm + 8] += outacc[mt][ntO][3];
        }
    } else {
        #pragma unroll
        for (int mt = 0; mt < 2; mt++)
        #pragma unroll
        for (int ntO = 0; ntO < 4; ntO++) {
            int rr0 = mt * 16 + gid;
            int c = ntO * 8 + tg * 2;
            float2* p0 = reinterpret_cast<float2*>(h + rr0 * 34 + c);
            float2 v0 = *p0;
            v0.x += outacc[mt][ntO][0]; v0.y += outacc[mt][ntO][1];
            *p0 = v0;
            float2* p1 = reinterpret_cast<float2*>(h + (rr0 + 8) * 34 + c);
            float2 v1 = *p1;
            v1.x += outacc[mt][ntO][2]; v1.y += outacc[mt][ntO][3];
            *p1 = v1;
        }
    }
    __syncwarp();
}

extern __shared__ char smem_raw[];

__global__ __launch_bounds__(NTHREADS, 1)
void mixer_kernel(
    const float* __restrict__ x,
    const float* __restrict__ conv_w, const float* __restrict__ conv_b,
    const float* __restrict__ fc0_w,  const float* __restrict__ fc0_b,
    const float* __restrict__ ln1_g,  const float* __restrict__ ln1_b,
    const float* __restrict__ w11,    const float* __restrict__ b11,
    const float* __restrict__ w12,    const float* __restrict__ b12,
    const float* __restrict__ ln2_g,  const float* __restrict__ ln2_b,
    const float* __restrict__ w21,    const float* __restrict__ b21,
    const float* __restrict__ w22,    const float* __restrict__ b22,
    const float* __restrict__ fc1_w,  const float* __restrict__ fc1_b,
    const float* __restrict__ fcout_w,const float* __restrict__ fcout_b,
    float* __restrict__ out, int B)
{
    const int tid = threadIdx.x;
    const int lane = tid & 31;
    const int wid = tid >> 5;      // 0..11, one element per warp

    float* sH   = reinterpret_cast<float*>(smem_raw + OFF_H);
    float* sSt  = reinterpret_cast<float*>(smem_raw + OFF_ST);
    float* sB1t = reinterpret_cast<float*>(smem_raw + OFF_B1T);
    float* sB1c = reinterpret_cast<float*>(smem_raw + OFF_B1C);
    float* sB2t = reinterpret_cast<float*>(smem_raw + OFF_B2T);
    float* sB2c = reinterpret_cast<float*>(smem_raw + OFF_B2C);
    float* sL1g = reinterpret_cast<float*>(smem_raw + OFF_LN1G);
    float* sL1b = reinterpret_cast<float*>(smem_raw + OFF_LN1B);
    float* sL2g = reinterpret_cast<float*>(smem_raw + OFF_LN2G);
    float* sL2b = reinterpret_cast<float*>(smem_raw + OFF_LN2B);
    __half* w1t = reinterpret_cast<__half*>(smem_raw + OFF_W1T);
    __half* w1c = reinterpret_cast<__half*>(smem_raw + OFF_W1C);
    __half* w2t = reinterpret_cast<__half*>(smem_raw + OFF_W2T);
    __half* w2c = reinterpret_cast<__half*>(smem_raw + OFF_W2C);
    float* sFw = reinterpret_cast<float*>(smem_raw + OFF_WT);
    float* sFo = reinterpret_cast<float*>(smem_raw + OFF_WT + 16384);

    const int eb = blockIdx.x * NWARPS + wid;
    const bool act = (eb < B);
    float* h  = sH + wid * (32 * 34);
    float* st = sSt + wid * 64;

    // ---- stage fc0 weights, preprocess (conv1x1 + fc0) ----
    for (int i = tid; i < 1024; i += NTHREADS) sFw[i] = fc0_w[i];
    if (tid < 32) sB1t[tid] = fc0_b[tid];
    __syncthreads();

    if (act) {
        const float cw0 = conv_w[0], cw1 = conv_w[1], cw2 = conv_w[2];
        const float cb  = conv_b[0];
        const float* xb = x + (size_t)eb * 3072 + lane * 32;
        float2 gp[16];
        #pragma unroll
        for (int qq = 0; qq < 8; qq++) {
            float4 v0 = *reinterpret_cast<const float4*>(xb + qq * 4);
            float4 v1 = *reinterpret_cast<const float4*>(xb + 1024 + qq * 4);
            float4 v2 = *reinterpret_cast<const float4*>(xb + 2048 + qq * 4);
            gp[2 * qq]     = make_float2(cw0 * v0.x + cw1 * v1.x + cw2 * v2.x + cb,
                                         cw0 * v0.y + cw1 * v1.y + cw2 * v2.y + cb);
            gp[2 * qq + 1] = make_float2(cw0 * v0.z + cw1 * v1.z + cw2 * v2.z + cb,
                                         cw0 * v0.w + cw1 * v1.w + cw2 * v2.w + cb);
        }
        for (int j = 0; j < 32; j++) {
            const float4* wq = reinterpret_cast<const float4*>(sFw + j * 32);
            float2 acc = make_float2(0.f, 0.f), accb = make_float2(0.f, 0.f);
            #pragma unroll
            for (int qq = 0; qq < 8; qq++) {
                float4 w = wq[qq];
                acc  = ffma2(gp[2 * qq],     make_float2(w.x, w.y), acc);
                accb = ffma2(gp[2 * qq + 1], make_float2(w.z, w.w), accb);
            }
            float2 sv = fadd2(acc, accb);
            h[lane * 34 + j] = sv.x + sv.y + sB1t[j];
        }
    }
    __syncthreads();

    // ---- 8 layers x 2 repeats ----
    for (int l = 0; l < 8; l++) {
        // stage fp16 hi/lo interleaved weight planes for this layer
        {
            const float* g11 = w11 + l * 8192;
            const float* g21 = w21 + l * 8192;
            for (int i = tid; i < 8192; i += NTHREADS) {
                int d = i >> 5, k = i & 31;
                int idx = d * 80 + (k >> 1) * 4 + (k & 1);
                float v = g11[i];
                __half hi = __float2half_rn(v);
                w1t[idx]     = hi;
                w1t[idx + 2] = __float2half_rn(v - __half2float(hi));
                float u = g21[i];
                __half hu = __float2half_rn(u);
                w1c[idx]     = hu;
                w1c[idx + 2] = __float2half_rn(u - __half2float(hu));
            }
            const float* g12 = w12 + l * 8192;
            const float* g22 = w22 + l * 8192;
            for (int i = tid; i < 8192; i += NTHREADS) {
                int n = i >> 8, k = i & 255;
                int idx = n * 528 + (k >> 1) * 4 + (k & 1);
                float v = g12[i] * (1.0f / 6.0f);
                __half hi = __float2half_rn(v);
                w2t[idx]     = hi;
                w2t[idx + 2] = __float2half_rn(v - __half2float(hi));
                float u = g22[i] * (1.0f / 6.0f);
                __half hu = __float2half_rn(u);
                w2c[idx]     = hu;
                w2c[idx + 2] = __float2half_rn(u - __half2float(hu));
            }
            if (tid < 256) { sB1t[tid] = b11[l * 256 + tid]; sB1c[tid] = b21[l * 256 + tid]; }
            if (tid < 32) {
                sB2t[tid] = b12[l * 32 + tid];
                sB2c[tid] = b22[l * 32 + tid];
                sL1g[tid] = ln1_g[l * 32 + tid];
                sL1b[tid] = ln1_b[l * 32 + tid];
                sL2g[tid] = ln2_g[l * 32 + tid];
                sL2b[tid] = ln2_b[l * 32 + tid];
            }
        }
        __syncthreads();

        if (act) {
            for (int rep = 0; rep < 2; rep++) {
                mix_branch_mma<true >(h, st, w1t, w2t, sB1t, sB2t, sL1g, sL1b, lane);
                mix_branch_mma<false>(h, st, w1c, w2c, sB1c, sB2c, sL2g, sL2b, lane);
            }
        }
        __syncthreads();
    }

    // ---- head: fc1 + hardswish + avgpool(32) + fcout ----
    {
        const float4* s1 = reinterpret_cast<const float4*>(fc1_w);
        float4* d1 = reinterpret_cast<float4*>(sFw);
        for (int i = tid; i < 1024; i += NTHREADS) d1[i] = s1[i];
        for (int i = tid; i < 1280; i += NTHREADS) sFo[i] = fcout_w[i];
        if (tid < 128) sB1t[tid] = fc1_b[tid];
        if (tid < 10)  sB2t[tid] = fcout_b[tid];
    }
    __syncthreads();

    if (act) {
        float2 ap[16];
        #pragma unroll
        for (int t = 0; t < 16; t++)
            ap[t] = *reinterpret_cast<const float2*>(h + lane * 34 + 2 * t);
        float pool[4] = {0.f, 0.f, 0.f, 0.f};
        for (int d = 0; d < 128; d++) {
            const float4* wq = reinterpret_cast<const float4*>(sFw + d * 32);
            float2 acc = make_float2(0.f, 0.f), accb = make_float2(0.f, 0.f);
            #pragma unroll
            for (int qq = 0; qq < 8; qq++) {
                float4 w = wq[qq];
                acc  = ffma2(ap[2 * qq],     make_float2(w.x, w.y), acc);
                accb = ffma2(ap[2 * qq + 1], make_float2(w.z, w.w), accb);
            }
            float2 sv = fadd2(acc, accb);
            float v = sv.x + sv.y + sB1t[d];
            float y = v * fminf(fmaxf(v + 3.0f, 0.0f), 6.0f) * (1.0f / 6.0f);
            pool[d >> 5] += y;
        }
        #pragma unroll
        for (int p = 0; p < 4; p++) pool[p] *= (1.0f / 32.0f);
        #pragma unroll
        for (int o = 0; o < 10; o++) {
            float4 wv = *reinterpret_cast<const float4*>(sFo + o * 128 + lane * 4);
            float v = pool[0] * wv.x + pool[1] * wv.y + pool[2] * wv.z + pool[3] * wv.w;
            #pragma unroll
            for (int sft = 16; sft > 0; sft >>= 1)
                v += __shfl_xor_sync(0xffffffffu, v, sft);
            if (lane == 0) out[(size_t)eb * 10 + o] = v + sB2t[o];
        }
    }
}

extern "C" void kernel_launch(void* const* d_in, const int* in_sizes, int n_in,
                              void* d_out, int out_size) {
    const float* x       = (const float*)d_in[0];
    const float* conv_w  = (const float*)d_in[1];
    const float* conv_b  = (const float*)d_in[2];
    const float* fc0_w   = (const float*)d_in[3];
    const float* fc0_b   = (const float*)d_in[4];
    const float* ln1_g   = (const float*)d_in[5];
    const float* ln1_b   = (const float*)d_in[6];
    const float* w11     = (const float*)d_in[7];
    const float* b11     = (const float*)d_in[8];
    const float* w12     = (const float*)d_in[9];
    const float* b12     = (const float*)d_in[10];
    const float* ln2_g   = (const float*)d_in[11];
    const float* ln2_b   = (const float*)d_in[12];
    const float* w21     = (const float*)d_in[13];
    const float* b21     = (const float*)d_in[14];
    const float* w22     = (const float*)d_in[15];
    const float* b22     = (const float*)d_in[16];
    const float* fc1_w   = (const float*)d_in[17];
    const float* fc1_b   = (const float*)d_in[18];
    const float* fcout_w = (const float*)d_in[19];
    const float* fcout_b = (const float*)d_in[20];
    float* out = (float*)d_out;

    const int B = in_sizes[0] / 3072;
    const int blocks = (B + NWARPS - 1) / NWARPS;

    cudaFuncSetAttribute(mixer_kernel,
                         cudaFuncAttributeMaxDynamicSharedMemorySize,
                         SMEM_BYTES);
    mixer_kernel<<<blocks, NTHREADS, SMEM_BYTES>>>(
        x, conv_w, conv_b, fc0_w, fc0_b, ln1_g, ln1_b,
        w11, b11, w12, b12, ln2_g, ln2_b, w21, b21, w22, b22,
        fc1_w, fc1_b, fcout_w, fcout_b, out, B);
}

// round 9
// speedup vs baseline: 2.0218x; 1.4663x over previous
#include <cuda_runtime.h>
#include <cuda_fp16.h>

// ---------------------------------------------------------------------------
// MLP-Mixer on tensor cores, round 8: SINGLE-pass fp16 (C = Ah @ Bh).
// Calibrated error model: activations-only rounding gave 2.88e-4; weight
// rounding adds an independent same-scale term -> predicted 4-6e-4 (< 1e-3).
// Weights staged pre-swizzled in MMA fragment order: one LDS.64 per
// (kt,nt) B-fragment feeding 2 MMAs. 256 MMAs/branch (was 512).
// 384 threads, 12 warps, one element per warp.
// Pre (conv+fc0) and head (fc1+pool+fcout) stay on the fp32 FFMA2 path.
// ---------------------------------------------------------------------------

#define MIX_EPS 1e-5f
#define NTHREADS 384
#define NWARPS 12

// ---- SMEM byte offsets ----
#define OFF_H     0         // 12 * 32*34 * 4 = 52224
#define OFF_ST    52224     // 12 * 64 * 4 = 3072
#define OFF_B1T   55296     // 256 f
#define OFF_B1C   56320
#define OFF_B2T   57344     // 32 f
#define OFF_B2C   57472
#define OFF_LN1G  57600
#define OFF_LN1B  57728
#define OFF_LN2G  57856
#define OFF_LN2B  57984
#define OFF_WT    58112     // weight region (also fp32 staging for pre/head)
#define OFF_W1T   58112     // 256 rows * 80 halves * 2B = 40960 (32 used/row)
#define OFF_W1C   99072     // 40960
#define OFF_W2T   140032    // 32 rows * 528 halves * 2B = 33792 (256 used/row)
#define OFF_W2C   173824    // 33792
#define SMEM_BYTES 207616

__device__ __forceinline__ float2 ffma2(float2 a, float2 b, float2 c) {
    unsigned long long au = *reinterpret_cast<unsigned long long*>(&a);
    unsigned long long bu = *reinterpret_cast<unsigned long long*>(&b);
    unsigned long long cu = *reinterpret_cast<unsigned long long*>(&c);
    unsigned long long du;
    asm("fma.rn.f32x2 %0, %1, %2, %3;" : "=l"(du) : "l"(au), "l"(bu), "l"(cu));
    return *reinterpret_cast<float2*>(&du);
}
__device__ __forceinline__ float2 fadd2(float2 a, float2 b) {
    unsigned long long au = *reinterpret_cast<unsigned long long*>(&a);
    unsigned long long bu = *reinterpret_cast<unsigned long long*>(&b);
    unsigned long long du;
    asm("add.rn.f32x2 %0, %1, %2;" : "=l"(du) : "l"(au), "l"(bu));
    return *reinterpret_cast<float2*>(&du);
}

__device__ __forceinline__ void mma16816(float d[4], const unsigned a[4],
                                         unsigned b0, unsigned b1) {
    asm volatile(
        "mma.sync.aligned.m16n8k16.row.col.f32.f16.f16.f32 "
        "{%0,%1,%2,%3}, {%4,%5,%6,%7}, {%8,%9}, {%0,%1,%2,%3};\n"
        : "+f"(d[0]), "+f"(d[1]), "+f"(d[2]), "+f"(d[3])
        : "r"(a[0]), "r"(a[1]), "r"(a[2]), "r"(a[3]), "r"(b0), "r"(b1));
}

// Fragment-swizzled weight layout (single fp16 plane):
//   w1: row n (256 rows), stride 80 halves (160 B). Slot s = kt*4 + tg at
//       halves offset s*4 holds [k(16kt+2tg), +1, k(16kt+2tg+8), +9].
//   w2: row n (32 rows), stride 528 halves (1056 B). Slot s = ktile*4 + tg,
//       ktile = k>>4 (0..15), same within-tile order.
// One uint2 (LDS.64) per fragment: f.x = b0, f.y = b1. w2 pre-scaled by 1/6.
template <bool TOKEN>
__device__ __forceinline__ void mix_branch_mma(
    float* h, float* st,
    const __half* w1, const __half* w2,
    const float* b1, const float* b2,
    const float* g, const float* bb, int lane)
{
    const int gid = lane >> 2;
    const int tg  = lane & 3;

    // ---- LN stats (lane = row) ----
    float s = 0.f, q = 0.f;
    #pragma unroll
    for (int j = 0; j < 32; j += 2) {
        float2 v = *reinterpret_cast<const float2*>(h + lane * 34 + j);
        s += v.x + v.y; q += v.x * v.x + v.y * v.y;
    }
    float m = s * 0.03125f;
    float r = rsqrtf(fmaxf(q * 0.03125f - m * m, 0.f) + MIX_EPS);
    st[lane] = m; st[32 + lane] = r;
    __syncwarp();

    // ---- A1 fragments (LN output, fp16) ----
    unsigned a1[2][2][4];
    #pragma unroll
    for (int mt = 0; mt < 2; mt++)
    #pragma unroll
    for (int kt = 0; kt < 2; kt++) {
        #pragma unroll
        for (int rr = 0; rr < 2; rr++) {
            int am = mt * 16 + gid + rr * 8;
            #pragma unroll
            for (int cc = 0; cc < 2; cc++) {
                int ak = kt * 16 + tg * 2 + cc * 8;
                float v0, v1;
                if (TOKEN) {
                    float x0 = h[ak * 34 + am];
                    float x1 = h[(ak + 1) * 34 + am];
                    float gm = g[am], bm = bb[am];
                    v0 = (x0 - st[ak]) * st[32 + ak] * gm + bm;
                    v1 = (x1 - st[ak + 1]) * st[32 + ak + 1] * gm + bm;
                } else {
                    float2 x = *reinterpret_cast<const float2*>(h + am * 34 + ak);
                    float mm = st[am], ri = st[32 + am];
                    v0 = (x.x - mm) * ri * g[ak] + bb[ak];
                    v1 = (x.y - mm) * ri * g[ak + 1] + bb[ak + 1];
                }
                __half2 hv = __floats2half2_rn(v0, v1);
                a1[mt][kt][rr + cc * 2] = *reinterpret_cast<unsigned*>(&hv);
            }
        }
    }

    // ---- out accumulators, init with bias b2 ----
    float outacc[2][4][4];
    #pragma unroll
    for (int ntO = 0; ntO < 4; ntO++) {
        int c = ntO * 8 + tg * 2;
        float bv0 = b2[c], bv1 = b2[c + 1];
        #pragma unroll
        for (int mt = 0; mt < 2; mt++) {
            outacc[mt][ntO][0] = bv0; outacc[mt][ntO][1] = bv1;
            outacc[mt][ntO][2] = bv0; outacc[mt][ntO][3] = bv1;
        }
    }

    // ---- hidden loop over DIM=256 in 4 chunks of 64 ----
    for (int nc = 0; nc < 4; nc++) {
        float dAcc[2][8][4];
        #pragma unroll
        for (int mt = 0; mt < 2; mt++)
        #pragma unroll
        for (int nt = 0; nt < 8; nt++)
        #pragma unroll
        for (int k = 0; k < 4; k++) dAcc[mt][nt][k] = 0.f;

        // gemm1: per (kt,nt): 1x LDS.64 -> 2 MMAs
        #pragma unroll
        for (int kt = 0; kt < 2; kt++) {
            #pragma unroll
            for (int nt = 0; nt < 8; nt++) {
                int n = nc * 64 + nt * 8 + gid;
                uint2 f = *reinterpret_cast<const uint2*>(
                    w1 + n * 80 + (kt * 4 + tg) * 4);
                mma16816(dAcc[0][nt], a1[0][kt], f.x, f.y);
                mma16816(dAcc[1][nt], a1[1][kt], f.x, f.y);
            }
        }

        // epilogue + gemm2, one kt2 (16 hidden cols) at a time
        #pragma unroll
        for (int kt2 = 0; kt2 < 4; kt2++) {
            unsigned a2[2][4];
            #pragma unroll
            for (int part = 0; part < 2; part++) {
                int nt = 2 * kt2 + part;
                int c = nc * 64 + nt * 8 + tg * 2;
                float2 bv = *reinterpret_cast<const float2*>(b1 + c);
                #pragma unroll
                for (int mt = 0; mt < 2; mt++) {
                    float v0 = dAcc[mt][nt][0] + bv.x;
                    float v1 = dAcc[mt][nt][1] + bv.y;
                    float v2 = dAcc[mt][nt][2] + bv.x;
                    float v3 = dAcc[mt][nt][3] + bv.y;
                    float h0 = v0 * fminf(fmaxf(v0 + 3.f, 0.f), 6.f);
                    float h1 = v1 * fminf(fmaxf(v1 + 3.f, 0.f), 6.f);
                    float h2 = v2 * fminf(fmaxf(v2 + 3.f, 0.f), 6.f);
                    float h3 = v3 * fminf(fmaxf(v3 + 3.f, 0.f), 6.f);
                    __half2 p01 = __floats2half2_rn(h0, h1);
                    __half2 p23 = __floats2half2_rn(h2, h3);
                    a2[mt][part * 2 + 0] = *reinterpret_cast<unsigned*>(&p01);
                    a2[mt][part * 2 + 1] = *reinterpret_cast<unsigned*>(&p23);
                }
            }
            #pragma unroll
            for (int ntO = 0; ntO < 4; ntO++) {
                int n = ntO * 8 + gid;
                int ktile = nc * 4 + kt2;
                uint2 f = *reinterpret_cast<const uint2*>(
                    w2 + n * 528 + (ktile * 4 + tg) * 4);
                mma16816(outacc[0][ntO], a2[0], f.x, f.y);
                mma16816(outacc[1][ntO], a2[1], f.x, f.y);
            }
        }
    }

    // ---- residual add back into h ----
    if (TOKEN) {
        #pragma unroll
        for (int mt = 0; mt < 2; mt++)
        #pragma unroll
        for (int ntO = 0; ntO < 4; ntO++) {
            int mm = mt * 16 + gid;
            int nn = ntO * 8 + tg * 2;
            h[nn * 34 + mm]           += outacc[mt][ntO][0];
            h[(nn + 1) * 34 + mm]     += outacc[mt][ntO][1];
            h[nn * 34 + mm + 8]       += outacc[mt][ntO][2];
            h[(nn + 1) * 34 + mm + 8] += outacc[mt][ntO][3];
        }
    } else {
        #pragma unroll
        for (int mt = 0; mt < 2; mt++)
        #pragma unroll
        for (int ntO = 0; ntO < 4; ntO++) {
            int rr0 = mt * 16 + gid;
            int c = ntO * 8 + tg * 2;
            float2* p0 = reinterpret_cast<float2*>(h + rr0 * 34 + c);
            float2 v0 = *p0;
            v0.x += outacc[mt][ntO][0]; v0.y += outacc[mt][ntO][1];
            *p0 = v0;
            float2* p1 = reinterpret_cast<float2*>(h + (rr0 + 8) * 34 + c);
            float2 v1 = *p1;
            v1.x += outacc[mt][ntO][2]; v1.y += outacc[mt][ntO][3];
            *p1 = v1;
        }
    }
    __syncwarp();
}

extern __shared__ char smem_raw[];

__global__ __launch_bounds__(NTHREADS, 1)
void mixer_kernel(
    const float* __restrict__ x,
    const float* __restrict__ conv_w, const float* __restrict__ conv_b,
    const float* __restrict__ fc0_w,  const float* __restrict__ fc0_b,
    const float* __restrict__ ln1_g,  const float* __restrict__ ln1_b,
    const float* __restrict__ w11,    const float* __restrict__ b11,
    const float* __restrict__ w12,    const float* __restrict__ b12,
    const float* __restrict__ ln2_g,  const float* __restrict__ ln2_b,
    const float* __restrict__ w21,    const float* __restrict__ b21,
    const float* __restrict__ w22,    const float* __restrict__ b22,
    const float* __restrict__ fc1_w,  const float* __restrict__ fc1_b,
    const float* __restrict__ fcout_w,const float* __restrict__ fcout_b,
    float* __restrict__ out, int B)
{
    const int tid = threadIdx.x;
    const int lane = tid & 31;
    const int wid = tid >> 5;      // 0..11, one element per warp

    float* sH   = reinterpret_cast<float*>(smem_raw + OFF_H);
    float* sSt  = reinterpret_cast<float*>(smem_raw + OFF_ST);
    float* sB1t = reinterpret_cast<float*>(smem_raw + OFF_B1T);
    float* sB1c = reinterpret_cast<float*>(smem_raw + OFF_B1C);
    float* sB2t = reinterpret_cast<float*>(smem_raw + OFF_B2T);
    float* sB2c = reinterpret_cast<float*>(smem_raw + OFF_B2C);
    float* sL1g = reinterpret_cast<float*>(smem_raw + OFF_LN1G);
    float* sL1b = reinterpret_cast<float*>(smem_raw + OFF_LN1B);
    float* sL2g = reinterpret_cast<float*>(smem_raw + OFF_LN2G);
    float* sL2b = reinterpret_cast<float*>(smem_raw + OFF_LN2B);
    __half* w1t = reinterpret_cast<__half*>(smem_raw + OFF_W1T);
    __half* w1c = reinterpret_cast<__half*>(smem_raw + OFF_W1C);
    __half* w2t = reinterpret_cast<__half*>(smem_raw + OFF_W2T);
    __half* w2c = reinterpret_cast<__half*>(smem_raw + OFF_W2C);
    float* sFw = reinterpret_cast<float*>(smem_raw + OFF_WT);
    float* sFo = reinterpret_cast<float*>(smem_raw + OFF_WT + 16384);

    const int eb = blockIdx.x * NWARPS + wid;
    const bool act = (eb < B);
    float* h  = sH + wid * (32 * 34);
    float* st = sSt + wid * 64;

    // ---- stage fc0 weights, preprocess (conv1x1 + fc0) ----
    for (int i = tid; i < 1024; i += NTHREADS) sFw[i] = fc0_w[i];
    if (tid < 32) sB1t[tid] = fc0_b[tid];
    __syncthreads();

    if (act) {
        const float cw0 = conv_w[0], cw1 = conv_w[1], cw2 = conv_w[2];
        const float cb  = conv_b[0];
        const float* xb = x + (size_t)eb * 3072 + lane * 32;
        float2 gp[16];
        #pragma unroll
        for (int qq = 0; qq < 8; qq++) {
            float4 v0 = *reinterpret_cast<const float4*>(xb + qq * 4);
            float4 v1 = *reinterpret_cast<const float4*>(xb + 1024 + qq * 4);
            float4 v2 = *reinterpret_cast<const float4*>(xb + 2048 + qq * 4);
            gp[2 * qq]     = make_float2(cw0 * v0.x + cw1 * v1.x + cw2 * v2.x + cb,
                                         cw0 * v0.y + cw1 * v1.y + cw2 * v2.y + cb);
            gp[2 * qq + 1] = make_float2(cw0 * v0.z + cw1 * v1.z + cw2 * v2.z + cb,
                                         cw0 * v0.w + cw1 * v1.w + cw2 * v2.w + cb);
        }
        for (int j = 0; j < 32; j++) {
            const float4* wq = reinterpret_cast<const float4*>(sFw + j * 32);
            float2 acc = make_float2(0.f, 0.f), accb = make_float2(0.f, 0.f);
            #pragma unroll
            for (int qq = 0; qq < 8; qq++) {
                float4 w = wq[qq];
                acc  = ffma2(gp[2 * qq],     make_float2(w.x, w.y), acc);
                accb = ffma2(gp[2 * qq + 1], make_float2(w.z, w.w), accb);
            }
            float2 sv = fadd2(acc, accb);
            h[lane * 34 + j] = sv.x + sv.y + sB1t[j];
        }
    }
    __syncthreads();

    // ---- 8 layers x 2 repeats ----
    for (int l = 0; l < 8; l++) {
        // stage fp16 fragment-swizzled weight planes for this layer
        {
            const float* g11 = w11 + l * 8192;
            const float* g21 = w21 + l * 8192;
            for (int i = tid; i < 8192; i += NTHREADS) {
                int d = i >> 5, k = i & 31;
                int kt = k >> 4, rrr = k & 15;
                int tgp, pos;
                if (rrr < 8) { tgp = rrr >> 1; pos = rrr & 1; }
                else         { tgp = (rrr - 8) >> 1; pos = 2 + (rrr & 1); }
                int idx = d * 80 + (kt * 4 + tgp) * 4 + pos;
                w1t[idx] = __float2half_rn(g11[i]);
                w1c[idx] = __float2half_rn(g21[i]);
            }
            const float* g12 = w12 + l * 8192;
            const float* g22 = w22 + l * 8192;
            for (int i = tid; i < 8192; i += NTHREADS) {
                int n = i >> 8, k = i & 255;
                int ktile = k >> 4, rrr = k & 15;
                int tgp, pos;
                if (rrr < 8) { tgp = rrr >> 1; pos = rrr & 1; }
                else         { tgp = (rrr - 8) >> 1; pos = 2 + (rrr & 1); }
                int idx = n * 528 + (ktile * 4 + tgp) * 4 + pos;
                w2t[idx] = __float2half_rn(g12[i] * (1.0f / 6.0f));
                w2c[idx] = __float2half_rn(g22[i] * (1.0f / 6.0f));
            }
            if (tid < 256) { sB1t[tid] = b11[l * 256 + tid]; sB1c[tid] = b21[l * 256 + tid]; }
            if (tid < 32) {
                sB2t[tid] = b12[l * 32 + tid];
                sB2c[tid] = b22[l * 32 + tid];
                sL1g[tid] = ln1_g[l * 32 + tid];
                sL1b[tid] = ln1_b[l * 32 + tid];
                sL2g[tid] = ln2_g[l * 32 + tid];
                sL2b[tid] = ln2_b[l * 32 + tid];
            }
        }
        __syncthreads();

        if (act) {
            for (int rep = 0; rep < 2; rep++) {
                mix_branch_mma<true >(h, st, w1t, w2t, sB1t, sB2t, sL1g, sL1b, lane);
                mix_branch_mma<false>(h, st, w1c, w2c, sB1c, sB2c, sL2g, sL2b, lane);
            }
        }
        __syncthreads();
    }

    // ---- head: fc1 + hardswish + avgpool(32) + fcout ----
    {
        const float4* s1 = reinterpret_cast<const float4*>(fc1_w);
        float4* d1 = reinterpret_cast<float4*>(sFw);
        for (int i = tid; i < 1024; i += NTHREADS) d1[i] = s1[i];
        for (int i = tid; i < 1280; i += NTHREADS) sFo[i] = fcout_w[i];
        if (tid < 128) sB1t[tid] = fc1_b[tid];
        if (tid < 10)  sB2t[tid] = fcout_b[tid];
    }
    __syncthreads();

    if (act) {
        float2 ap[16];
        #pragma unroll
        for (int t = 0; t < 16; t++)
            ap[t] = *reinterpret_cast<const float2*>(h + lane * 34 + 2 * t);
        float pool[4] = {0.f, 0.f, 0.f, 0.f};
        for (int d = 0; d < 128; d++) {
            const float4* wq = reinterpret_cast<const float4*>(sFw + d * 32);
            float2 acc = make_float2(0.f, 0.f), accb = make_float2(0.f, 0.f);
            #pragma unroll
            for (int qq = 0; qq < 8; qq++) {
                float4 w = wq[qq];
                acc  = ffma2(ap[2 * qq],     make_float2(w.x, w.y), acc);
                accb = ffma2(ap[2 * qq + 1], make_float2(w.z, w.w), accb);
            }
            float2 sv = fadd2(acc, accb);
            float v = sv.x + sv.y + sB1t[d];
            float y = v * fminf(fmaxf(v + 3.0f, 0.0f), 6.0f) * (1.0f / 6.0f);
            pool[d >> 5] += y;
        }
        #pragma unroll
        for (int p = 0; p < 4; p++) pool[p] *= (1.0f / 32.0f);
        #pragma unroll
        for (int o = 0; o < 10; o++) {
            float4 wv = *reinterpret_cast<const float4*>(sFo + o * 128 + lane * 4);
            float v = pool[0] * wv.x + pool[1] * wv.y + pool[2] * wv.z + pool[3] * wv.w;
            #pragma unroll
            for (int sft = 16; sft > 0; sft >>= 1)
                v += __shfl_xor_sync(0xffffffffu, v, sft);
            if (lane == 0) out[(size_t)eb * 10 + o] = v + sB2t[o];
        }
    }
}

extern "C" void kernel_launch(void* const* d_in, const int* in_sizes, int n_in,
                              void* d_out, int out_size) {
    const float* x       = (const float*)d_in[0];
    const float* conv_w  = (const float*)d_in[1];
    const float* conv_b  = (const float*)d_in[2];
    const float* fc0_w   = (const float*)d_in[3];
    const float* fc0_b   = (const float*)d_in[4];
    const float* ln1_g   = (const float*)d_in[5];
    const float* ln1_b   = (const float*)d_in[6];
    const float* w11     = (const float*)d_in[7];
    const float* b11     = (const float*)d_in[8];
    const float* w12     = (const float*)d_in[9];
    const float* b12     = (const float*)d_in[10];
    const float* ln2_g   = (const float*)d_in[11];
    const float* ln2_b   = (const float*)d_in[12];
    const float* w21     = (const float*)d_in[13];
    const float* b21     = (const float*)d_in[14];
    const float* w22     = (const float*)d_in[15];
    const float* b22     = (const float*)d_in[16];
    const float* fc1_w   = (const float*)d_in[17];
    const float* fc1_b   = (const float*)d_in[18];
    const float* fcout_w = (const float*)d_in[19];
    const float* fcout_b = (const float*)d_in[20];
    float* out = (float*)d_out;

    const int B = in_sizes[0] / 3072;
    const int blocks = (B + NWARPS - 1) / NWARPS;

    cudaFuncSetAttribute(mixer_kernel,
                         cudaFuncAttributeMaxDynamicSharedMemorySize,
                         SMEM_BYTES);
    mixer_kernel<<<blocks, NTHREADS, SMEM_BYTES>>>(
        x, conv_w, conv_b, fc0_w, fc0_b, ln1_g, ln1_b,
        w11, b11, w12, b12, ln2_g, ln2_b, w21, b21, w22, b22,
        fc1_w, fc1_b, fcout_w, fcout_b, out, B);
}

// round 10
// speedup vs baseline: 2.1147x; 1.0460x over previous
#include <cuda_runtime.h>
#include <cuda_fp16.h>

// ---------------------------------------------------------------------------
// MLP-Mixer on tensor cores, round 9: single-pass fp16 (C = Ah @ Bh), now at
// 512 threads / 16 warps / 16 elems per CTA (4 warps/SMSP; 128 regs x 512 thr
// = full 64K RF). SMEM slimmed via tighter conflict-free weight strides
// (48 / 272 halves, stride = 8 mod 32 words => disjoint bank spans per gid).
// b1 bias folded into MMA accumulator init. Fragment-swizzled weights:
// one LDS.64 per B-fragment feeding 2 MMAs.
// Pre (conv+fc0) and head (fc1+pool+fcout) stay on the fp32 FFMA2 path.
// ---------------------------------------------------------------------------

#define MIX_EPS 1e-5f
#define NTHREADS 512
#define NWARPS 16

// ---- SMEM byte offsets ----
#define OFF_H     0         // 16 * 32*34 * 4 = 69632
#define OFF_ST    69632     // 16 * 64 * 4 = 4096
#define OFF_B1T   73728     // 256 f
#define OFF_B1C   74752
#define OFF_B2T   75776     // 32 f
#define OFF_B2C   75904
#define OFF_LN1G  76032
#define OFF_LN1B  76160
#define OFF_LN2G  76288
#define OFF_LN2B  76416
#define OFF_WT    76544     // weight region (also fp32 staging for pre/head)
#define OFF_W1T   76544     // 256 rows * 48 halves * 2B = 24576
#define OFF_W1C   101120    // 24576
#define OFF_W2T   125696    // 32 rows * 272 halves * 2B = 17408
#define OFF_W2C   143104    // 17408
#define SMEM_BYTES 160512

__device__ __forceinline__ float2 ffma2(float2 a, float2 b, float2 c) {
    unsigned long long au = *reinterpret_cast<unsigned long long*>(&a);
    unsigned long long bu = *reinterpret_cast<unsigned long long*>(&b);
    unsigned long long cu = *reinterpret_cast<unsigned long long*>(&c);
    unsigned long long du;
    asm("fma.rn.f32x2 %0, %1, %2, %3;" : "=l"(du) : "l"(au), "l"(bu), "l"(cu));
    return *reinterpret_cast<float2*>(&du);
}
__device__ __forceinline__ float2 fadd2(float2 a, float2 b) {
    unsigned long long au = *reinterpret_cast<unsigned long long*>(&a);
    unsigned long long bu = *reinterpret_cast<unsigned long long*>(&b);
    unsigned long long du;
    asm("add.rn.f32x2 %0, %1, %2;" : "=l"(du) : "l"(au), "l"(bu));
    return *reinterpret_cast<float2*>(&du);
}

__device__ __forceinline__ void mma16816(float d[4], const unsigned a[4],
                                         unsigned b0, unsigned b1) {
    asm volatile(
        "mma.sync.aligned.m16n8k16.row.col.f32.f16.f16.f32 "
        "{%0,%1,%2,%3}, {%4,%5,%6,%7}, {%8,%9}, {%0,%1,%2,%3};\n"
        : "+f"(d[0]), "+f"(d[1]), "+f"(d[2]), "+f"(d[3])
        : "r"(a[0]), "r"(a[1]), "r"(a[2]), "r"(a[3]), "r"(b0), "r"(b1));
}

// Fragment-swizzled weight layout (single fp16 plane):
//   w1: row n (256 rows), stride 48 halves (96 B). Slot s = kt*4 + tg at
//       halves offset s*4 holds [k(16kt+2tg), +1, k(16kt+2tg+8), +9].
//   w2: row n (32 rows), stride 272 halves (544 B). Slot s = ktile*4 + tg,
//       ktile = k>>4 (0..15), same within-tile order.
// One uint2 (LDS.64) per fragment: f.x = b0, f.y = b1. w2 pre-scaled by 1/6.
template <bool TOKEN>
__device__ __forceinline__ void mix_branch_mma(
    float* h, float* st,
    const __half* w1, const __half* w2,
    const float* b1, const float* b2,
    const float* g, const float* bb, int lane)
{
    const int gid = lane >> 2;
    const int tg  = lane & 3;

    // ---- LN stats (lane = row) ----
    float s = 0.f, q = 0.f;
    #pragma unroll
    for (int j = 0; j < 32; j += 2) {
        float2 v = *reinterpret_cast<const float2*>(h + lane * 34 + j);
        s += v.x + v.y; q += v.x * v.x + v.y * v.y;
    }
    float m = s * 0.03125f;
    float r = rsqrtf(fmaxf(q * 0.03125f - m * m, 0.f) + MIX_EPS);
    st[lane] = m; st[32 + lane] = r;
    __syncwarp();

    // ---- A1 fragments (LN output, fp16) ----
    unsigned a1[2][2][4];
    #pragma unroll
    for (int mt = 0; mt < 2; mt++)
    #pragma unroll
    for (int kt = 0; kt < 2; kt++) {
        #pragma unroll
        for (int rr = 0; rr < 2; rr++) {
            int am = mt * 16 + gid + rr * 8;
            #pragma unroll
            for (int cc = 0; cc < 2; cc++) {
                int ak = kt * 16 + tg * 2 + cc * 8;
                float v0, v1;
                if (TOKEN) {
                    float x0 = h[ak * 34 + am];
                    float x1 = h[(ak + 1) * 34 + am];
                    float gm = g[am], bm = bb[am];
                    v0 = (x0 - st[ak]) * st[32 + ak] * gm + bm;
                    v1 = (x1 - st[ak + 1]) * st[32 + ak + 1] * gm + bm;
                } else {
                    float2 x = *reinterpret_cast<const float2*>(h + am * 34 + ak);
                    float mm = st[am], ri = st[32 + am];
                    v0 = (x.x - mm) * ri * g[ak] + bb[ak];
                    v1 = (x.y - mm) * ri * g[ak + 1] + bb[ak + 1];
                }
                __half2 hv = __floats2half2_rn(v0, v1);
                a1[mt][kt][rr + cc * 2] = *reinterpret_cast<unsigned*>(&hv);
            }
        }
    }

    // ---- out accumulators, init with bias b2 ----
    float outacc[2][4][4];
    #pragma unroll
    for (int ntO = 0; ntO < 4; ntO++) {
        int c = ntO * 8 + tg * 2;
        float bv0 = b2[c], bv1 = b2[c + 1];
        #pragma unroll
        for (int mt = 0; mt < 2; mt++) {
            outacc[mt][ntO][0] = bv0; outacc[mt][ntO][1] = bv1;
            outacc[mt][ntO][2] = bv0; outacc[mt][ntO][3] = bv1;
        }
    }

    // ---- hidden loop over DIM=256 in 4 chunks of 64 ----
    for (int nc = 0; nc < 4; nc++) {
        // dAcc init with b1 bias (per hidden column)
        float dAcc[2][8][4];
        #pragma unroll
        for (int nt = 0; nt < 8; nt++) {
            float2 bv = *reinterpret_cast<const float2*>(
                b1 + nc * 64 + nt * 8 + tg * 2);
            #pragma unroll
            for (int mt = 0; mt < 2; mt++) {
                dAcc[mt][nt][0] = bv.x; dAcc[mt][nt][1] = bv.y;
                dAcc[mt][nt][2] = bv.x; dAcc[mt][nt][3] = bv.y;
            }
        }

        // gemm1: per (kt,nt): 1x LDS.64 -> 2 MMAs
        #pragma unroll
        for (int kt = 0; kt < 2; kt++) {
            #pragma unroll
            for (int nt = 0; nt < 8; nt++) {
                int n = nc * 64 + nt * 8 + gid;
                uint2 f = *reinterpret_cast<const uint2*>(
                    w1 + n * 48 + (kt * 4 + tg) * 4);
                mma16816(dAcc[0][nt], a1[0][kt], f.x, f.y);
                mma16816(dAcc[1][nt], a1[1][kt], f.x, f.y);
            }
        }

        // epilogue + gemm2, one kt2 (16 hidden cols) at a time
        #pragma unroll
        for (int kt2 = 0; kt2 < 4; kt2++) {
            unsigned a2[2][4];
            #pragma unroll
            for (int part = 0; part < 2; part++) {
                int nt = 2 * kt2 + part;
                #pragma unroll
                for (int mt = 0; mt < 2; mt++) {
                    float v0 = dAcc[mt][nt][0];
                    float v1 = dAcc[mt][nt][1];
                    float v2 = dAcc[mt][nt][2];
                    float v3 = dAcc[mt][nt][3];
                    float h0 = v0 * fminf(fmaxf(v0 + 3.f, 0.f), 6.f);
                    float h1 = v1 * fminf(fmaxf(v1 + 3.f, 0.f), 6.f);
                    float h2 = v2 * fminf(fmaxf(v2 + 3.f, 0.f), 6.f);
                    float h3 = v3 * fminf(fmaxf(v3 + 3.f, 0.f), 6.f);
                    __half2 p01 = __floats2half2_rn(h0, h1);
                    __half2 p23 = __floats2half2_rn(h2, h3);
                    a2[mt][part * 2 + 0] = *reinterpret_cast<unsigned*>(&p01);
                    a2[mt][part * 2 + 1] = *reinterpret_cast<unsigned*>(&p23);
                }
            }
            #pragma unroll
            for (int ntO = 0; ntO < 4; ntO++) {
                int n = ntO * 8 + gid;
                int ktile = nc * 4 + kt2;
                uint2 f = *reinterpret_cast<const uint2*>(
                    w2 + n * 272 + (ktile * 4 + tg) * 4);
                mma16816(outacc[0][ntO], a2[0], f.x, f.y);
                mma16816(outacc[1][ntO], a2[1], f.x, f.y);
            }
        }
    }

    // ---- residual add back into h ----
    if (TOKEN) {
        #pragma unroll
        for (int mt = 0; mt < 2; mt++)
        #pragma unroll
        for (int ntO = 0; ntO < 4; ntO++) {
            int mm = mt * 16 + gid;
            int nn = ntO * 8 + tg * 2;
            h[nn * 34 + mm]           += outacc[mt][ntO][0];
            h[(nn + 1) * 34 + mm]     += outacc[mt][ntO][1];
            h[nn * 34 + mm + 8]       += outacc[mt][ntO][2];
            h[(nn + 1) * 34 + mm + 8] += outacc[mt][ntO][3];
        }
    } else {
        #pragma unroll
        for (int mt = 0; mt < 2; mt++)
        #pragma unroll
        for (int ntO = 0; ntO < 4; ntO++) {
            int rr0 = mt * 16 + gid;
            int c = ntO * 8 + tg * 2;
            float2* p0 = reinterpret_cast<float2*>(h + rr0 * 34 + c);
            float2 v0 = *p0;
            v0.x += outacc[mt][ntO][0]; v0.y += outacc[mt][ntO][1];
            *p0 = v0;
            float2* p1 = reinterpret_cast<float2*>(h + (rr0 + 8) * 34 + c);
            float2 v1 = *p1;
            v1.x += outacc[mt][ntO][2]; v1.y += outacc[mt][ntO][3];
            *p1 = v1;
        }
    }
    __syncwarp();
}

extern __shared__ char smem_raw[];

__global__ __launch_bounds__(NTHREADS, 1)
void mixer_kernel(
    const float* __restrict__ x,
    const float* __restrict__ conv_w, const float* __restrict__ conv_b,
    const float* __restrict__ fc0_w,  const float* __restrict__ fc0_b,
    const float* __restrict__ ln1_g,  const float* __restrict__ ln1_b,
    const float* __restrict__ w11,    const float* __restrict__ b11,
    const float* __restrict__ w12,    const float* __restrict__ b12,
    const float* __restrict__ ln2_g,  const float* __restrict__ ln2_b,
    const float* __restrict__ w21,    const float* __restrict__ b21,
    const float* __restrict__ w22,    const float* __restrict__ b22,
    const float* __restrict__ fc1_w,  const float* __restrict__ fc1_b,
    const float* __restrict__ fcout_w,const float* __restrict__ fcout_b,
    float* __restrict__ out, int B)
{
    const int tid = threadIdx.x;
    const int lane = tid & 31;
    const int wid = tid >> 5;      // 0..15, one element per warp

    float* sH   = reinterpret_cast<float*>(smem_raw + OFF_H);
    float* sSt  = reinterpret_cast<float*>(smem_raw + OFF_ST);
    float* sB1t = reinterpret_cast<float*>(smem_raw + OFF_B1T);
    float* sB1c = reinterpret_cast<float*>(smem_raw + OFF_B1C);
    float* sB2t = reinterpret_cast<float*>(smem_raw + OFF_B2T);
    float* sB2c = reinterpret_cast<float*>(smem_raw + OFF_B2C);
    float* sL1g = reinterpret_cast<float*>(smem_raw + OFF_LN1G);
    float* sL1b = reinterpret_cast<float*>(smem_raw + OFF_LN1B);
    float* sL2g = reinterpret_cast<float*>(smem_raw + OFF_LN2G);
    float* sL2b = reinterpret_cast<float*>(smem_raw + OFF_LN2B);
    __half* w1t = reinterpret_cast<__half*>(smem_raw + OFF_W1T);
    __half* w1c = reinterpret_cast<__half*>(smem_raw + OFF_W1C);
    __half* w2t = reinterpret_cast<__half*>(smem_raw + OFF_W2T);
    __half* w2c = reinterpret_cast<__half*>(smem_raw + OFF_W2C);
    float* sFw = reinterpret_cast<float*>(smem_raw + OFF_WT);
    float* sFo = reinterpret_cast<float*>(smem_raw + OFF_WT + 16384);

    const int eb = blockIdx.x * NWARPS + wid;
    const bool act = (eb < B);
    float* h  = sH + wid * (32 * 34);
    float* st = sSt + wid * 64;

    // ---- stage fc0 weights, preprocess (conv1x1 + fc0) ----
    for (int i = tid; i < 1024; i += NTHREADS) sFw[i] = fc0_w[i];
    if (tid < 32) sB1t[tid] = fc0_b[tid];
    __syncthreads();

    if (act) {
        const float cw0 = conv_w[0], cw1 = conv_w[1], cw2 = conv_w[2];
        const float cb  = conv_b[0];
        const float* xb = x + (size_t)eb * 3072 + lane * 32;
        float2 gp[16];
        #pragma unroll
        for (int qq = 0; qq < 8; qq++) {
            float4 v0 = *reinterpret_cast<const float4*>(xb + qq * 4);
            float4 v1 = *reinterpret_cast<const float4*>(xb + 1024 + qq * 4);
            float4 v2 = *reinterpret_cast<const float4*>(xb + 2048 + qq * 4);
            gp[2 * qq]     = make_float2(cw0 * v0.x + cw1 * v1.x + cw2 * v2.x + cb,
                                         cw0 * v0.y + cw1 * v1.y + cw2 * v2.y + cb);
            gp[2 * qq + 1] = make_float2(cw0 * v0.z + cw1 * v1.z + cw2 * v2.z + cb,
                                         cw0 * v0.w + cw1 * v1.w + cw2 * v2.w + cb);
        }
        for (int j = 0; j < 32; j++) {
            const float4* wq = reinterpret_cast<const float4*>(sFw + j * 32);
            float2 acc = make_float2(0.f, 0.f), accb = make_float2(0.f, 0.f);
            #pragma unroll
            for (int qq = 0; qq < 8; qq++) {
                float4 w = wq[qq];
                acc  = ffma2(gp[2 * qq],     make_float2(w.x, w.y), acc);
                accb = ffma2(gp[2 * qq + 1], make_float2(w.z, w.w), accb);
            }
            float2 sv = fadd2(acc, accb);
            h[lane * 34 + j] = sv.x + sv.y + sB1t[j];
        }
    }
    __syncthreads();

    // ---- 8 layers x 2 repeats ----
    for (int l = 0; l < 8; l++) {
        // stage fp16 fragment-swizzled weight planes for this layer
        {
            const float* g11 = w11 + l * 8192;
            const float* g21 = w21 + l * 8192;
            for (int i = tid; i < 8192; i += NTHREADS) {
                int d = i >> 5, k = i & 31;
                int kt = k >> 4, rrr = k & 15;
                int tgp, pos;
                if (rrr < 8) { tgp = rrr >> 1; pos = rrr & 1; }
                else         { tgp = (rrr - 8) >> 1; pos = 2 + (rrr & 1); }
                int idx = d * 48 + (kt * 4 + tgp) * 4 + pos;
                w1t[idx] = __float2half_rn(g11[i]);
                w1c[idx] = __float2half_rn(g21[i]);
            }
            const float* g12 = w12 + l * 8192;
            const float* g22 = w22 + l * 8192;
            for (int i = tid; i < 8192; i += NTHREADS) {
                int n = i >> 8, k = i & 255;
                int ktile = k >> 4, rrr = k & 15;
                int tgp, pos;
                if (rrr < 8) { tgp = rrr >> 1; pos = rrr & 1; }
                else         { tgp = (rrr - 8) >> 1; pos = 2 + (rrr & 1); }
                int idx = n * 272 + (ktile * 4 + tgp) * 4 + pos;
                w2t[idx] = __float2half_rn(g12[i] * (1.0f / 6.0f));
                w2c[idx] = __float2half_rn(g22[i] * (1.0f / 6.0f));
            }
            if (tid < 256) { sB1t[tid] = b11[l * 256 + tid]; sB1c[tid] = b21[l * 256 + tid]; }
            if (tid < 32) {
                sB2t[tid] = b12[l * 32 + tid];
                sB2c[tid] = b22[l * 32 + tid];
                sL1g[tid] = ln1_g[l * 32 + tid];
                sL1b[tid] = ln1_b[l * 32 + tid];
                sL2g[tid] = ln2_g[l * 32 + tid];
                sL2b[tid] = ln2_b[l * 32 + tid];
            }
        }
        __syncthreads();

        if (act) {
            for (int rep = 0; rep < 2; rep++) {
                mix_branch_mma<true >(h, st, w1t, w2t, sB1t, sB2t, sL1g, sL1b, lane);
                mix_branch_mma<false>(h, st, w1c, w2c, sB1c, sB2c, sL2g, sL2b, lane);
            }
        }
        __syncthreads();
    }

    // ---- head: fc1 + hardswish + avgpool(32) + fcout ----
    {
        const float4* s1 = reinterpret_cast<const float4*>(fc1_w);
        float4* d1 = reinterpret_cast<float4*>(sFw);
        for (int i = tid; i < 1024; i += NTHREADS) d1[i] = s1[i];
        for (int i = tid; i < 1280; i += NTHREADS) sFo[i] = fcout_w[i];
        if (tid < 128) sB1t[tid] = fc1_b[tid];
        if (tid < 10)  sB2t[tid] = fcout_b[tid];
    }
    __syncthreads();

    if (act) {
        float2 ap[16];
        #pragma unroll
        for (int t = 0; t < 16; t++)
            ap[t] = *reinterpret_cast<const float2*>(h + lane * 34 + 2 * t);
        float pool[4] = {0.f, 0.f, 0.f, 0.f};
        for (int d = 0; d < 128; d++) {
            const float4* wq = reinterpret_cast<const float4*>(sFw + d * 32);
            float2 acc = make_float2(0.f, 0.f), accb = make_float2(0.f, 0.f);
            #pragma unroll
            for (int qq = 0; qq < 8; qq++) {
                float4 w = wq[qq];
                acc  = ffma2(ap[2 * qq],     make_float2(w.x, w.y), acc);
                accb = ffma2(ap[2 * qq + 1], make_float2(w.z, w.w), accb);
            }
            float2 sv = fadd2(acc, accb);
            float v = sv.x + sv.y + sB1t[d];
            float y = v * fminf(fmaxf(v + 3.0f, 0.0f), 6.0f) * (1.0f / 6.0f);
            pool[d >> 5] += y;
        }
        #pragma unroll
        for (int p = 0; p < 4; p++) pool[p] *= (1.0f / 32.0f);
        #pragma unroll
        for (int o = 0; o < 10; o++) {
            float4 wv = *reinterpret_cast<const float4*>(sFo + o * 128 + lane * 4);
            float v = pool[0] * wv.x + pool[1] * wv.y + pool[2] * wv.z + pool[3] * wv.w;
            #pragma unroll
            for (int sft = 16; sft > 0; sft >>= 1)
                v += __shfl_xor_sync(0xffffffffu, v, sft);
            if (lane == 0) out[(size_t)eb * 10 + o] = v + sB2t[o];
        }
    }
}

extern "C" void kernel_launch(void* const* d_in, const int* in_sizes, int n_in,
                              void* d_out, int out_size) {
    const float* x       = (const float*)d_in[0];
    const float* conv_w  = (const float*)d_in[1];
    const float* conv_b  = (const float*)d_in[2];
    const float* fc0_w   = (const float*)d_in[3];
    const float* fc0_b   = (const float*)d_in[4];
    const float* ln1_g   = (const float*)d_in[5];
    const float* ln1_b   = (const float*)d_in[6];
    const float* w11     = (const float*)d_in[7];
    const float* b11     = (const float*)d_in[8];
    const float* w12     = (const float*)d_in[9];
    const float* b12     = (const float*)d_in[10];
    const float* ln2_g   = (const float*)d_in[11];
    const float* ln2_b   = (const float*)d_in[12];
    const float* w21     = (const float*)d_in[13];
    const float* b21     = (const float*)d_in[14];
    const float* w22     = (const float*)d_in[15];
    const float* b22     = (const float*)d_in[16];
    const float* fc1_w   = (const float*)d_in[17];
    const float* fc1_b   = (const float*)d_in[18];
    const float* fcout_w = (const float*)d_in[19];
    const float* fcout_b = (const float*)d_in[20];
    float* out = (float*)d_out;

    const int B = in_sizes[0] / 3072;
    const int blocks = (B + NWARPS - 1) / NWARPS;

    cudaFuncSetAttribute(mixer_kernel,
                         cudaFuncAttributeMaxDynamicSharedMemorySize,
                         SMEM_BYTES);
    mixer_kernel<<<blocks, NTHREADS, SMEM_BYTES>>>(
        x, conv_w, conv_b, fc0_w, fc0_b, ln1_g, ln1_b,
        w11, b11, w12, b12, ln2_g, ln2_b, w21, b21, w22, b22,
        fc1_w, fc1_b, fcout_w, fcout_b, out, B);
}

// round 11
// speedup vs baseline: 2.4036x; 1.1366x over previous
#include <cuda_runtime.h>
#include <cuda_fp16.h>

// ---------------------------------------------------------------------------
// MLP-Mixer on tensor cores, round 10: single-pass fp16 (C = Ah @ Bh).
// 512 threads / 16 warps / 16 elems per CTA. New this round:
//  (a) LDS.128 weight fragments — w1 packed rows (32 halves) put both
//      kt-fragments contiguous; w2 rows (stride 288 halves, 144 words = 16
//      mod 32, conflict-free) pair consecutive kt2 fragments. One LDS.128
//      feeds 4 MMAs (halves mainloop LDS + address-IMAD count).
//  (b) half2 epilogue — hswish computed in packed half2 (HADD2/HMNMX2/HMUL2),
//      halving epilogue scalar ops. w2 pre-scaled by 1/6.
// Pre (conv+fc0) and head (fc1+pool+fcout) stay on the fp32 FFMA2 path.
// ---------------------------------------------------------------------------

#define MIX_EPS 1e-5f
#define NTHREADS 512
#define NWARPS 16

// ---- SMEM byte offsets ----
#define OFF_H     0         // 16 * 32*34 * 4 = 69632
#define OFF_ST    69632     // 16 * 64 * 4 = 4096
#define OFF_B1T   73728     // 256 f
#define OFF_B1C   74752
#define OFF_B2T   75776     // 32 f
#define OFF_B2C   75904
#define OFF_LN1G  76032
#define OFF_LN1B  76160
#define OFF_LN2G  76288
#define OFF_LN2B  76416
#define OFF_WT    76544     // weight region (also fp32 staging for pre/head)
#define OFF_W1T   76544     // 256 rows * 32 halves * 2B = 16384
#define OFF_W1C   92928     // 16384
#define OFF_W2T   109312    // 32 rows * 288 halves * 2B = 18432
#define OFF_W2C   127744    // 18432
#define SMEM_BYTES 146176

__device__ __forceinline__ float2 ffma2(float2 a, float2 b, float2 c) {
    unsigned long long au = *reinterpret_cast<unsigned long long*>(&a);
    unsigned long long bu = *reinterpret_cast<unsigned long long*>(&b);
    unsigned long long cu = *reinterpret_cast<unsigned long long*>(&c);
    unsigned long long du;
    asm("fma.rn.f32x2 %0, %1, %2, %3;" : "=l"(du) : "l"(au), "l"(bu), "l"(cu));
    return *reinterpret_cast<float2*>(&du);
}
__device__ __forceinline__ float2 fadd2(float2 a, float2 b) {
    unsigned long long au = *reinterpret_cast<unsigned long long*>(&a);
    unsigned long long bu = *reinterpret_cast<unsigned long long*>(&b);
    unsigned long long du;
    asm("add.rn.f32x2 %0, %1, %2;" : "=l"(du) : "l"(au), "l"(bu));
    return *reinterpret_cast<float2*>(&du);
}

__device__ __forceinline__ void mma16816(float d[4], const unsigned a[4],
                                         unsigned b0, unsigned b1) {
    asm volatile(
        "mma.sync.aligned.m16n8k16.row.col.f32.f16.f16.f32 "
        "{%0,%1,%2,%3}, {%4,%5,%6,%7}, {%8,%9}, {%0,%1,%2,%3};\n"
        : "+f"(d[0]), "+f"(d[1]), "+f"(d[2]), "+f"(d[3])
        : "r"(a[0]), "r"(a[1]), "r"(a[2]), "r"(a[3]), "r"(b0), "r"(b1));
}

// hswish (without 1/6) on two packed fp16 values.
__device__ __forceinline__ __half2 hswish2(__half2 v) {
    const __half2 three = __floats2half2_rn(3.f, 3.f);
    const __half2 six   = __floats2half2_rn(6.f, 6.f);
    const __half2 zero  = __floats2half2_rn(0.f, 0.f);
    __half2 c = __hmin2(__hmax2(__hadd2(v, three), zero), six);
    return __hmul2(v, c);
}

// Fragment-swizzled weight layout (single fp16 plane):
//   w1: row n (256 rows), 32 halves packed. Group tg (0..3) at halves tg*8:
//       [kt0 frag: k(2tg),k(2tg+1),k(2tg+8),k(2tg+9) | kt1 frag: +16 each].
//       One LDS.128 per (nc,nt) -> both kt fragments -> 4 MMAs.
//   w2: row n (32 rows), stride 288 halves (144 words = 16 mod 32). Group
//       (pair,tg) at halves (pair*4+tg)*8, pair = ktile>>1; within group
//       [even-ktile frag | odd-ktile frag]. One LDS.128 per (j,ntO) -> 2 kt2.
// w2 pre-scaled by 1/6.
template <bool TOKEN>
__device__ __forceinline__ void mix_branch_mma(
    float* h, float* st,
    const __half* w1, const __half* w2,
    const float* b1, const float* b2,
    const float* g, const float* bb, int lane)
{
    const int gid = lane >> 2;
    const int tg  = lane & 3;

    // ---- LN stats (lane = row) ----
    float s = 0.f, q = 0.f;
    #pragma unroll
    for (int j = 0; j < 32; j += 2) {
        float2 v = *reinterpret_cast<const float2*>(h + lane * 34 + j);
        s += v.x + v.y; q += v.x * v.x + v.y * v.y;
    }
    float m = s * 0.03125f;
    float r = rsqrtf(fmaxf(q * 0.03125f - m * m, 0.f) + MIX_EPS);
    st[lane] = m; st[32 + lane] = r;
    __syncwarp();

    // ---- A1 fragments (LN output, fp16) ----
    unsigned a1[2][2][4];
    #pragma unroll
    for (int mt = 0; mt < 2; mt++)
    #pragma unroll
    for (int kt = 0; kt < 2; kt++) {
        #pragma unroll
        for (int rr = 0; rr < 2; rr++) {
            int am = mt * 16 + gid + rr * 8;
            #pragma unroll
            for (int cc = 0; cc < 2; cc++) {
                int ak = kt * 16 + tg * 2 + cc * 8;
                float v0, v1;
                if (TOKEN) {
                    float x0 = h[ak * 34 + am];
                    float x1 = h[(ak + 1) * 34 + am];
                    float gm = g[am], bm = bb[am];
                    v0 = (x0 - st[ak]) * st[32 + ak] * gm + bm;
                    v1 = (x1 - st[ak + 1]) * st[32 + ak + 1] * gm + bm;
                } else {
                    float2 x = *reinterpret_cast<const float2*>(h + am * 34 + ak);
                    float mm = st[am], ri = st[32 + am];
                    v0 = (x.x - mm) * ri * g[ak] + bb[ak];
                    v1 = (x.y - mm) * ri * g[ak + 1] + bb[ak + 1];
                }
                __half2 hv = __floats2half2_rn(v0, v1);
                a1[mt][kt][rr + cc * 2] = *reinterpret_cast<unsigned*>(&hv);
            }
        }
    }

    // ---- out accumulators, init with bias b2 ----
    float outacc[2][4][4];
    #pragma unroll
    for (int ntO = 0; ntO < 4; ntO++) {
        int c = ntO * 8 + tg * 2;
        float bv0 = b2[c], bv1 = b2[c + 1];
        #pragma unroll
        for (int mt = 0; mt < 2; mt++) {
            outacc[mt][ntO][0] = bv0; outacc[mt][ntO][1] = bv1;
            outacc[mt][ntO][2] = bv0; outacc[mt][ntO][3] = bv1;
        }
    }

    // ---- hidden loop over DIM=256 in 4 chunks of 64 ----
    for (int nc = 0; nc < 4; nc++) {
        // dAcc init with b1 bias (per hidden column)
        float dAcc[2][8][4];
        #pragma unroll
        for (int nt = 0; nt < 8; nt++) {
            float2 bv = *reinterpret_cast<const float2*>(
                b1 + nc * 64 + nt * 8 + tg * 2);
            #pragma unroll
            for (int mt = 0; mt < 2; mt++) {
                dAcc[mt][nt][0] = bv.x; dAcc[mt][nt][1] = bv.y;
                dAcc[mt][nt][2] = bv.x; dAcc[mt][nt][3] = bv.y;
            }
        }

        // gemm1: per nt one LDS.128 (both kt fragments) -> 4 MMAs
        #pragma unroll
        for (int nt = 0; nt < 8; nt++) {
            int n = nc * 64 + nt * 8 + gid;
            uint4 f = *reinterpret_cast<const uint4*>(w1 + n * 32 + tg * 8);
            mma16816(dAcc[0][nt], a1[0][0], f.x, f.y);
            mma16816(dAcc[1][nt], a1[1][0], f.x, f.y);
            mma16816(dAcc[0][nt], a1[0][1], f.z, f.w);
            mma16816(dAcc[1][nt], a1[1][1], f.z, f.w);
        }

        // epilogue + gemm2: j indexes kt2 pairs; one LDS.128 per (j,ntO)
        #pragma unroll
        for (int j = 0; j < 2; j++) {
            uint4 fw[4];
            #pragma unroll
            for (int ntO = 0; ntO < 4; ntO++) {
                int n = ntO * 8 + gid;
                fw[ntO] = *reinterpret_cast<const uint4*>(
                    w2 + n * 288 + ((nc * 2 + j) * 4 + tg) * 8);
            }
            #pragma unroll
            for (int p = 0; p < 2; p++) {
                int kt2 = 2 * j + p;
                unsigned a2[2][4];
                #pragma unroll
                for (int part = 0; part < 2; part++) {
                    int nt = 2 * kt2 + part;
                    #pragma unroll
                    for (int mt = 0; mt < 2; mt++) {
                        __half2 ha = __floats2half2_rn(dAcc[mt][nt][0],
                                                       dAcc[mt][nt][1]);
                        __half2 hb = __floats2half2_rn(dAcc[mt][nt][2],
                                                       dAcc[mt][nt][3]);
                        __half2 ra = hswish2(ha);
                        __half2 rb = hswish2(hb);
                        a2[mt][part * 2 + 0] = *reinterpret_cast<unsigned*>(&ra);
                        a2[mt][part * 2 + 1] = *reinterpret_cast<unsigned*>(&rb);
                    }
                }
                #pragma unroll
                for (int ntO = 0; ntO < 4; ntO++) {
                    unsigned b0 = p ? fw[ntO].z : fw[ntO].x;
                    unsigned b1r = p ? fw[ntO].w : fw[ntO].y;
                    mma16816(outacc[0][ntO], a2[0], b0, b1r);
                    mma16816(outacc[1][ntO], a2[1], b0, b1r);
                }
            }
        }
    }

    // ---- residual add back into h ----
    if (TOKEN) {
        #pragma unroll
        for (int mt = 0; mt < 2; mt++)
        #pragma unroll
        for (int ntO = 0; ntO < 4; ntO++) {
            int mm = mt * 16 + gid;
            int nn = ntO * 8 + tg * 2;
            h[nn * 34 + mm]           += outacc[mt][ntO][0];
            h[(nn + 1) * 34 + mm]     += outacc[mt][ntO][1];
            h[nn * 34 + mm + 8]       += outacc[mt][ntO][2];
            h[(nn + 1) * 34 + mm + 8] += outacc[mt][ntO][3];
        }
    } else {
        #pragma unroll
        for (int mt = 0; mt < 2; mt++)
        #pragma unroll
        for (int ntO = 0; ntO < 4; ntO++) {
            int rr0 = mt * 16 + gid;
            int c = ntO * 8 + tg * 2;
            float2* p0 = reinterpret_cast<float2*>(h + rr0 * 34 + c);
            float2 v0 = *p0;
            v0.x += outacc[mt][ntO][0]; v0.y += outacc[mt][ntO][1];
            *p0 = v0;
            float2* p1 = reinterpret_cast<float2*>(h + (rr0 + 8) * 34 + c);
            float2 v1 = *p1;
            v1.x += outacc[mt][ntO][2]; v1.y += outacc[mt][ntO][3];
            *p1 = v1;
        }
    }
    __syncwarp();
}

extern __shared__ char smem_raw[];

__global__ __launch_bounds__(NTHREADS, 1)
void mixer_kernel(
    const float* __restrict__ x,
    const float* __restrict__ conv_w, const float* __restrict__ conv_b,
    const float* __restrict__ fc0_w,  const float* __restrict__ fc0_b,
    const float* __restrict__ ln1_g,  const float* __restrict__ ln1_b,
    const float* __restrict__ w11,    const float* __restrict__ b11,
    const float* __restrict__ w12,    const float* __restrict__ b12,
    const float* __restrict__ ln2_g,  const float* __restrict__ ln2_b,
    const float* __restrict__ w21,    const float* __restrict__ b21,
    const float* __restrict__ w22,    const float* __restrict__ b22,
    const float* __restrict__ fc1_w,  const float* __restrict__ fc1_b,
    const float* __restrict__ fcout_w,const float* __restrict__ fcout_b,
    float* __restrict__ out, int B)
{
    const int tid = threadIdx.x;
    const int lane = tid & 31;
    const int wid = tid >> 5;      // 0..15, one element per warp

    float* sH   = reinterpret_cast<float*>(smem_raw + OFF_H);
    float* sSt  = reinterpret_cast<float*>(smem_raw + OFF_ST);
    float* sB1t = reinterpret_cast<float*>(smem_raw + OFF_B1T);
    float* sB1c = reinterpret_cast<float*>(smem_raw + OFF_B1C);
    float* sB2t = reinterpret_cast<float*>(smem_raw + OFF_B2T);
    float* sB2c = reinterpret_cast<float*>(smem_raw + OFF_B2C);
    float* sL1g = reinterpret_cast<float*>(smem_raw + OFF_LN1G);
    float* sL1b = reinterpret_cast<float*>(smem_raw + OFF_LN1B);
    float* sL2g = reinterpret_cast<float*>(smem_raw + OFF_LN2G);
    float* sL2b = reinterpret_cast<float*>(smem_raw + OFF_LN2B);
    __half* w1t = reinterpret_cast<__half*>(smem_raw + OFF_W1T);
    __half* w1c = reinterpret_cast<__half*>(smem_raw + OFF_W1C);
    __half* w2t = reinterpret_cast<__half*>(smem_raw + OFF_W2T);
    __half* w2c = reinterpret_cast<__half*>(smem_raw + OFF_W2C);
    float* sFw = reinterpret_cast<float*>(smem_raw + OFF_WT);
    float* sFo = reinterpret_cast<float*>(smem_raw + OFF_W1C);

    const int eb = blockIdx.x * NWARPS + wid;
    const bool act = (eb < B);
    float* h  = sH + wid * (32 * 34);
    float* st = sSt + wid * 64;

    // ---- stage fc0 weights, preprocess (conv1x1 + fc0) ----
    for (int i = tid; i < 1024; i += NTHREADS) sFw[i] = fc0_w[i];
    if (tid < 32) sB1t[tid] = fc0_b[tid];
    __syncthreads();

    if (act) {
        const float cw0 = conv_w[0], cw1 = conv_w[1], cw2 = conv_w[2];
        const float cb  = conv_b[0];
        const float* xb = x + (size_t)eb * 3072 + lane * 32;
        float2 gp[16];
        #pragma unroll
        for (int qq = 0; qq < 8; qq++) {
            float4 v0 = *reinterpret_cast<const float4*>(xb + qq * 4);
            float4 v1 = *reinterpret_cast<const float4*>(xb + 1024 + qq * 4);
            float4 v2 = *reinterpret_cast<const float4*>(xb + 2048 + qq * 4);
            gp[2 * qq]     = make_float2(cw0 * v0.x + cw1 * v1.x + cw2 * v2.x + cb,
                                         cw0 * v0.y + cw1 * v1.y + cw2 * v2.y + cb);
            gp[2 * qq + 1] = make_float2(cw0 * v0.z + cw1 * v1.z + cw2 * v2.z + cb,
                                         cw0 * v0.w + cw1 * v1.w + cw2 * v2.w + cb);
        }
        for (int j = 0; j < 32; j++) {
            const float4* wq = reinterpret_cast<const float4*>(sFw + j * 32);
            float2 acc = make_float2(0.f, 0.f), accb = make_float2(0.f, 0.f);
            #pragma unroll
            for (int qq = 0; qq < 8; qq++) {
                float4 w = wq[qq];
                acc  = ffma2(gp[2 * qq],     make_float2(w.x, w.y), acc);
                accb = ffma2(gp[2 * qq + 1], make_float2(w.z, w.w), accb);
            }
            float2 sv = fadd2(acc, accb);
            h[lane * 34 + j] = sv.x + sv.y + sB1t[j];
        }
    }
    __syncthreads();

    // ---- 8 layers x 2 repeats ----
    for (int l = 0; l < 8; l++) {
        // stage fp16 fragment-swizzled weight planes for this layer
        {
            const float* g11 = w11 + l * 8192;
            const float* g21 = w21 + l * 8192;
            for (int i = tid; i < 8192; i += NTHREADS) {
                int d = i >> 5, k = i & 31;
                int kt = k >> 4, rrr = k & 15;
                int tgp, pos;
                if (rrr < 8) { tgp = rrr >> 1; pos = rrr & 1; }
                else         { tgp = (rrr - 8) >> 1; pos = 2 + (rrr & 1); }
                int idx = d * 32 + tgp * 8 + kt * 4 + pos;
                w1t[idx] = __float2half_rn(g11[i]);
                w1c[idx] = __float2half_rn(g21[i]);
            }
            const float* g12 = w12 + l * 8192;
            const float* g22 = w22 + l * 8192;
            for (int i = tid; i < 8192; i += NTHREADS) {
                int n = i >> 8, k = i & 255;
                int ktile = k >> 4, rrr = k & 15;
                int tgp, pos;
                if (rrr < 8) { tgp = rrr >> 1; pos = rrr & 1; }
                else         { tgp = (rrr - 8) >> 1; pos = 2 + (rrr & 1); }
                int idx = n * 288 + ((ktile >> 1) * 4 + tgp) * 8
                          + (ktile & 1) * 4 + pos;
                w2t[idx] = __float2half_rn(g12[i] * (1.0f / 6.0f));
                w2c[idx] = __float2half_rn(g22[i] * (1.0f / 6.0f));
            }
            if (tid < 256) { sB1t[tid] = b11[l * 256 + tid]; sB1c[tid] = b21[l * 256 + tid]; }
            if (tid < 32) {
                sB2t[tid] = b12[l * 32 + tid];
                sB2c[tid] = b22[l * 32 + tid];
                sL1g[tid] = ln1_g[l * 32 + tid];
                sL1b[tid] = ln1_b[l * 32 + tid];
                sL2g[tid] = ln2_g[l * 32 + tid];
                sL2b[tid] = ln2_b[l * 32 + tid];
            }
        }
        __syncthreads();

        if (act) {
            for (int rep = 0; rep < 2; rep++) {
                mix_branch_mma<true >(h, st, w1t, w2t, sB1t, sB2t, sL1g, sL1b, lane);
                mix_branch_mma<false>(h, st, w1c, w2c, sB1c, sB2c, sL2g, sL2b, lane);
            }
        }
        __syncthreads();
    }

    // ---- head: fc1 + hardswish + avgpool(32) + fcout ----
    {
        const float4* s1 = reinterpret_cast<const float4*>(fc1_w);
        float4* d1 = reinterpret_cast<float4*>(sFw);
        for (int i = tid; i < 1024; i += NTHREADS) d1[i] = s1[i];
        for (int i = tid; i < 1280; i += NTHREADS) sFo[i] = fcout_w[i];
        if (tid < 128) sB1t[tid] = fc1_b[tid];
        if (tid < 10)  sB2t[tid] = fcout_b[tid];
    }
    __syncthreads();

    if (act) {
        float2 ap[16];
        #pragma unroll
        for (int t = 0; t < 16; t++)
            ap[t] = *reinterpret_cast<const float2*>(h + lane * 34 + 2 * t);
        float pool[4] = {0.f, 0.f, 0.f, 0.f};
        for (int d = 0; d < 128; d++) {
            const float4* wq = reinterpret_cast<const float4*>(sFw + d * 32);
            float2 acc = make_float2(0.f, 0.f), accb = make_float2(0.f, 0.f);
            #pragma unroll
            for (int qq = 0; qq < 8; qq++) {
                float4 w = wq[qq];
                acc  = ffma2(ap[2 * qq],     make_float2(w.x, w.y), acc);
                accb = ffma2(ap[2 * qq + 1], make_float2(w.z, w.w), accb);
            }
            float2 sv = fadd2(acc, accb);
            float v = sv.x + sv.y + sB1t[d];
            float y = v * fminf(fmaxf(v + 3.0f, 0.0f), 6.0f) * (1.0f / 6.0f);
            pool[d >> 5] += y;
        }
        #pragma unroll
        for (int p = 0; p < 4; p++) pool[p] *= (1.0f / 32.0f);
        #pragma unroll
        for (int o = 0; o < 10; o++) {
            float4 wv = *reinterpret_cast<const float4*>(sFo + o * 128 + lane * 4);
            float v = pool[0] * wv.x + pool[1] * wv.y + pool[2] * wv.z + pool[3] * wv.w;
            #pragma unroll
            for (int sft = 16; sft > 0; sft >>= 1)
                v += __shfl_xor_sync(0xffffffffu, v, sft);
            if (lane == 0) out[(size_t)eb * 10 + o] = v + sB2t[o];
        }
    }
}

extern "C" void kernel_launch(void* const* d_in, const int* in_sizes, int n_in,
                              void* d_out, int out_size) {
    const float* x       = (const float*)d_in[0];
    const float* conv_w  = (const float*)d_in[1];
    const float* conv_b  = (const float*)d_in[2];
    const float* fc0_w   = (const float*)d_in[3];
    const float* fc0_b   = (const float*)d_in[4];
    const float* ln1_g   = (const float*)d_in[5];
    const float* ln1_b   = (const float*)d_in[6];
    const float* w11     = (const float*)d_in[7];
    const float* b11     = (const float*)d_in[8];
    const float* w12     = (const float*)d_in[9];
    const float* b12     = (const float*)d_in[10];
    const float* ln2_g   = (const float*)d_in[11];
    const float* ln2_b   = (const float*)d_in[12];
    const float* w21     = (const float*)d_in[13];
    const float* b21     = (const float*)d_in[14];
    const float* w22     = (const float*)d_in[15];
    const float* b22     = (const float*)d_in[16];
    const float* fc1_w   = (const float*)d_in[17];
    const float* fc1_b   = (const float*)d_in[18];
    const float* fcout_w = (const float*)d_in[19];
    const float* fcout_b = (const float*)d_in[20];
    float* out = (float*)d_out;

    const int B = in_sizes[0] / 3072;
    const int blocks = (B + NWARPS - 1) / NWARPS;

    cudaFuncSetAttribute(mixer_kernel,
                         cudaFuncAttributeMaxDynamicSharedMemorySize,
                         SMEM_BYTES);
    mixer_kernel<<<blocks, NTHREADS, SMEM_BYTES>>>(
        x, conv_w, conv_b, fc0_w, fc0_b, ln1_g, ln1_b,
        w11, b11, w12, b12, ln2_g, ln2_b, w21, b21, w22, b22,
        fc1_w, fc1_b, fcout_w, fcout_b, out, B);
}